// round 7
// baseline (speedup 1.0000x reference)
#include <cuda_runtime.h>
#include <cuda_bf16.h>
#include <math.h>
#include <stdint.h>

// ===========================================================================
// AttentionLayer via mma.sync bf16 split GEMMs (fp32 accumulate in registers)
// B=64, T=1024, S=1024, C=E=512. Output = concat(out [B,T,C], attn [B,T,S])
//
// fp32 operand x split hi+lo bf16, stored [hi|lo] (2K columns). GEMM runs a
// 3-section logical K (sections remapped by the loader):
//   secs A: hi, lo, hi   secs B: hi, hi, lo
//   C = Ahi·Bhi + Alo·Bhi + Ahi·Blo  ≈ A·B  (err ~2^-18)
//
// GEMM: CTA tile 128x256, 8 warps (2m x 4n), warp tile m64xn64,
//       4-stage cp.async pipeline (48KB/stage = 192KB smem), 1 CTA/SM.
// ===========================================================================

static const float SQRT_HALF_F = 0.70710678118654752440f;

// ------------------------------ scratch ------------------------------------
__device__ __nv_bfloat16 g_xsplit  [(size_t)65536 * 1024];
__device__ __nv_bfloat16 g_hsplit  [(size_t)65536 * 1024];
__device__ __nv_bfloat16 g_ctxsplit[(size_t)65536 * 1024];
__device__ __nv_bfloat16 g_attnsplit[(size_t)65536 * 2048];
__device__ __nv_bfloat16 g_esumT   [(size_t)64 * 1024 * 1024];
__device__ __nv_bfloat16 g_enc2T   [(size_t)64 * 512 * 2048];
__device__ __nv_bfloat16 g_winsplit [512 * 1024];
__device__ __nv_bfloat16 g_woutsplit[512 * 1024];

// ------------------------------ helpers ------------------------------------
__device__ __forceinline__ uint32_t smem_u32(const void* p) {
    uint32_t a;
    asm("{ .reg .u64 t; cvta.to.shared.u64 t, %1; cvt.u32.u64 %0, t; }"
        : "=r"(a) : "l"(p));
    return a;
}

// pack two floats -> bf16x2 (first arg at lower address)
__device__ __forceinline__ uint32_t f2bf2(float lo, float hi) {
    uint32_t r;
    asm("cvt.rn.bf16x2.f32 %0, %1, %2;" : "=r"(r) : "f"(hi), "f"(lo));
    return r;
}
__device__ __forceinline__ float bfround(float v) {
    return __bfloat162float(__float2bfloat16(v));
}

__device__ __forceinline__ void cp16(uint32_t s, const void* g) {
    asm volatile("cp.async.cg.shared.global [%0], [%1], 16;" :: "r"(s), "l"(g));
}

__device__ __forceinline__ void ldsm4(uint32_t* r, uint32_t addr) {
    asm volatile("ldmatrix.sync.aligned.m8n8.x4.shared.b16 {%0,%1,%2,%3}, [%4];"
                 : "=r"(r[0]), "=r"(r[1]), "=r"(r[2]), "=r"(r[3]) : "r"(addr));
}

__device__ __forceinline__ void mma16816(float* d, const uint32_t* a,
                                         uint32_t b0, uint32_t b1) {
    asm volatile(
        "mma.sync.aligned.m16n8k16.row.col.f32.bf16.bf16.f32 "
        "{%0,%1,%2,%3}, {%4,%5,%6,%7}, {%8,%9}, {%0,%1,%2,%3};"
        : "+f"(d[0]), "+f"(d[1]), "+f"(d[2]), "+f"(d[3])
        : "r"(a[0]), "r"(a[1]), "r"(a[2]), "r"(a[3]), "r"(b0), "r"(b1));
}

// ===========================================================================
// weight-norm + split [hi|lo]: one block per row, cols=512
// ===========================================================================
__global__ void wn_split_kernel(const float* __restrict__ v, const float* __restrict__ g,
                                __nv_bfloat16* __restrict__ w, int cols)
{
    int r = blockIdx.x;
    int tid = threadIdx.x;
    const float* vr = v + (size_t)r * cols;

    float ss = 0.f;
    for (int c = tid; c < cols; c += blockDim.x) { float t = vr[c]; ss += t * t; }
    __shared__ float sm[32];
    #pragma unroll
    for (int o = 16; o > 0; o >>= 1) ss += __shfl_down_sync(0xffffffffu, ss, o);
    int warp = tid >> 5, lane = tid & 31;
    if (lane == 0) sm[warp] = ss;
    __syncthreads();
    int nw = blockDim.x >> 5;
    if (warp == 0) {
        float s2 = (lane < nw) ? sm[lane] : 0.f;
        #pragma unroll
        for (int o = 16; o > 0; o >>= 1) s2 += __shfl_down_sync(0xffffffffu, s2, o);
        if (lane == 0) sm[0] = s2;
    }
    __syncthreads();
    float scale = g[r] / sqrtf(sm[0]);
    __nv_bfloat16* wr = w + (size_t)r * (2 * cols);
    for (int c = tid; c < cols; c += blockDim.x) {
        float wv = vr[c] * scale;
        __nv_bfloat16 h = __float2bfloat16(wv);
        __nv_bfloat16 l = __float2bfloat16(wv - __bfloat162float(h));
        wr[c] = h;
        wr[cols + c] = l;
    }
}

// ===========================================================================
// A-split [hi|lo]:  x [65536,512] -> [65536,1024]
// ===========================================================================
__global__ void asplit_kernel(const float* __restrict__ in, __nv_bfloat16* __restrict__ out)
{
    size_t idx = (size_t)blockIdx.x * 256 + threadIdx.x;
    size_t row = idx >> 6;
    int g = (int)(idx & 63);
    const float* p = in + row * 512 + g * 8;
    float4 f0 = *(const float4*)p;
    float4 f1 = *(const float4*)(p + 4);
    float v[8] = {f0.x, f0.y, f0.z, f0.w, f1.x, f1.y, f1.z, f1.w};
    uint32_t hi[4], lo[4];
    #pragma unroll
    for (int q = 0; q < 4; q++) {
        hi[q] = f2bf2(v[2*q], v[2*q+1]);
        lo[q] = f2bf2(v[2*q] - bfround(v[2*q]), v[2*q+1] - bfround(v[2*q+1]));
    }
    __nv_bfloat16* o = out + row * 1024 + g * 8;
    *(uint4*)(o)       = *(uint4*)hi;
    *(uint4*)(o + 512) = *(uint4*)lo;
}

// ===========================================================================
// transpose + split [hi|lo]: in (optionally in0+in1) [R, Cc] -> out [Cc, 2R]
// ===========================================================================
__global__ void transpose_split_kernel(const float* __restrict__ in0,
                                       const float* __restrict__ in1,
                                       __nv_bfloat16* __restrict__ out,
                                       int R, int Cc, long long sIn, long long sOut)
{
    __shared__ float tile[64][33];
    int b = blockIdx.z;
    const float* A0 = in0 + (size_t)b * sIn;
    const float* A1 = in1 ? in1 + (size_t)b * sIn : nullptr;
    __nv_bfloat16* O = out + (size_t)b * sOut;
    int r0 = blockIdx.x * 64;
    int c0 = blockIdx.y * 32;
    int tid = threadIdx.x;

    #pragma unroll
    for (int i = 0; i < 8; i++) {
        int idx = i * 256 + tid;
        int rr = idx >> 5, cc = idx & 31;
        size_t off = (size_t)(r0 + rr) * Cc + c0 + cc;
        float vv = A0[off];
        if (A1) vv += A1[off];
        tile[rr][cc] = vv;
    }
    __syncthreads();

    int j = tid >> 3;
    int g = tid & 7;
    float v[8];
    #pragma unroll
    for (int u = 0; u < 8; u++) v[u] = tile[g * 8 + u][j];
    uint32_t hi[4], lo[4];
    #pragma unroll
    for (int p = 0; p < 4; p++) {
        hi[p] = f2bf2(v[2*p], v[2*p+1]);
        lo[p] = f2bf2(v[2*p] - bfround(v[2*p]), v[2*p+1] - bfround(v[2*p+1]));
    }
    __nv_bfloat16* ob = O + (size_t)(c0 + j) * (2 * R) + r0 + g * 8;
    *(uint4*)(ob)     = *(uint4*)hi;
    *(uint4*)(ob + R) = *(uint4*)lo;
}

// ===========================================================================
// mma.sync GEMM: C[128x256] = A x B^T over 3 remapped K-sections, fp32 accum.
// A stored [M, 2*KLOG] as [hi|lo]; B stored [N, 2*KLOG] as [hi|lo].
// Section maps: A {hi,lo,hi}, B {hi,hi,lo}.
// 8 warps (2m x 4n), warp tile m64 x n64. 4-stage cp.async pipeline.
// EPI: 0 = f32 C=acc*scale ; 1 = f32 C=(acc+bias+addend)*scale
//      2 = split [hi|lo] C=acc*scale ; 3 = split (acc+bias+addend)*scale
// ===========================================================================
#define SMEM_BYTES 196608   // 4 stages x (16KB A + 32KB B)
#define STAGE_SZ   49152

template <int EPI, int KLOG>
__global__ __launch_bounds__(256, 1)
void mma_gemm(const __nv_bfloat16* __restrict__ A,
              const __nv_bfloat16* __restrict__ B,
              float* __restrict__ Cf, __nv_bfloat16* __restrict__ Cs,
              int N,
              long long sA, long long sB, long long sC,
              const float* __restrict__ bias,
              const float* __restrict__ addend,
              float scale)
{
    constexpr int K2E    = 2 * KLOG;       // stored row length (elements)
    constexpr int SECLEN = KLOG / 64;      // chunks per section
    constexpr int NUMK   = 3 * SECLEN;

    extern __shared__ __align__(1024) char smem[];
    uint32_t sbase = smem_u32(smem);

    int tid = threadIdx.x, wid = tid >> 5, lane = tid & 31;
    int z = blockIdx.z;
    A += (size_t)z * sA;
    B += (size_t)z * sB;
    if (EPI <= 1) Cf += (size_t)z * sC; else Cs += (size_t)z * sC;
    int m0 = blockIdx.y * 128, n0 = blockIdx.x * 256;
    int warpM = (wid >> 2) * 64, warpN = (wid & 3) * 64;

    // ---- loader mapping ----
    // A: 128 rows x 128B = 4 cp16/thread ; B: 256 rows x 128B = 8 cp16/thread
    int c = tid & 7, rbase = tid >> 3;     // rbase 0..31
    const size_t rs = (size_t)32 * K2E * 2;   // 32 rows in bytes
    const char* aRow = (const char*)(A + (size_t)(m0 + rbase) * K2E + c * 8);
    const char* bRow = (const char*)(B + (size_t)(n0 + rbase) * K2E + c * 8);
    uint32_t swo[8];
    #pragma unroll
    for (int i = 0; i < 8; i++) {
        uint32_t bo = (uint32_t)(rbase + 32 * i) * 128 + c * 16;
        swo[i] = bo ^ ((bo >> 3) & 0x70);
    }

    // per-chunk byte offsets via section remap
    auto koffA = [](int ck) -> size_t {
        int sec = ck / SECLEN;
        int kk  = ck - sec * SECLEN;
        int map = (sec == 1) ? 1 : 0;          // A: hi, lo, hi
        return ((size_t)map * KLOG + (size_t)kk * 64) * 2;
    };
    auto koffB = [](int ck) -> size_t {
        int sec = ck / SECLEN;
        int kk  = ck - sec * SECLEN;
        int map = (sec == 2) ? 1 : 0;          // B: hi, hi, lo
        return ((size_t)map * KLOG + (size_t)kk * 64) * 2;
    };

#define LOADCHUNK(STG, CK) do {                                            \
        size_t oa_ = koffA(CK), ob_ = koffB(CK);                           \
        uint32_t ab_ = (STG), bb_ = (STG) + 16384;                         \
        cp16(ab_ + swo[0], aRow + oa_);                                    \
        cp16(ab_ + swo[1], aRow + oa_ + rs);                               \
        cp16(ab_ + swo[2], aRow + oa_ + 2 * rs);                           \
        cp16(ab_ + swo[3], aRow + oa_ + 3 * rs);                           \
        cp16(bb_ + swo[0], bRow + ob_);                                    \
        cp16(bb_ + swo[1], bRow + ob_ + rs);                               \
        cp16(bb_ + swo[2], bRow + ob_ + 2 * rs);                           \
        cp16(bb_ + swo[3], bRow + ob_ + 3 * rs);                           \
        cp16(bb_ + swo[4], bRow + ob_ + 4 * rs);                           \
        cp16(bb_ + swo[5], bRow + ob_ + 5 * rs);                           \
        cp16(bb_ + swo[6], bRow + ob_ + 6 * rs);                           \
        cp16(bb_ + swo[7], bRow + ob_ + 7 * rs);                           \
        asm volatile("cp.async.commit_group;" ::: "memory");               \
    } while (0)

    // ---- ldmatrix per-lane swizzled offsets ----
    uint32_t aoff[4], boff[4];
    {
        int l = lane;
        #pragma unroll
        for (int mt = 0; mt < 4; mt++) {
            int row = warpM + mt * 16 + (l & 15);
            uint32_t cb = (uint32_t)((l >> 4) << 4);
            aoff[mt] = (uint32_t)row * 128 + (cb ^ (((uint32_t)row & 7) << 4));
        }
        #pragma unroll
        for (int ng = 0; ng < 4; ng++) {
            int row = warpN + ng * 16 + (l & 7) + ((l >> 4) << 3);
            uint32_t cb = (uint32_t)(((l >> 3) & 1) << 4);
            boff[ng] = (uint32_t)row * 128 + (cb ^ (((uint32_t)row & 7) << 4));
        }
    }

    float d[4][8][4];
    #pragma unroll
    for (int mt = 0; mt < 4; mt++)
        #pragma unroll
        for (int nt = 0; nt < 8; nt++)
            #pragma unroll
            for (int q = 0; q < 4; q++) d[mt][nt][q] = 0.f;

    // prologue: chunks 0..2 into stages 0..2
    LOADCHUNK(sbase,                0);
    if (NUMK > 1) LOADCHUNK(sbase + STAGE_SZ,     1);
    if (NUMK > 2) LOADCHUNK(sbase + 2 * STAGE_SZ, 2);

    for (int ck = 0; ck < NUMK; ck++) {
        // groups outstanding: ck..min(ck+2, NUMK-1); ensure ck's is done
        if (ck + 2 < NUMK)      asm volatile("cp.async.wait_group 2;" ::: "memory");
        else if (ck + 1 < NUMK) asm volatile("cp.async.wait_group 1;" ::: "memory");
        else                    asm volatile("cp.async.wait_group 0;" ::: "memory");
        __syncthreads();   // data visible + stage (ck+3)%4 free (compute ck-1 done)

        if (ck + 3 < NUMK)
            LOADCHUNK(sbase + (uint32_t)((ck + 3) & 3) * STAGE_SZ, ck + 3);

        uint32_t stg = sbase + (uint32_t)(ck & 3) * STAGE_SZ;
        uint32_t ab = stg, bb = stg + 16384;
        #pragma unroll
        for (int ks = 0; ks < 4; ks++) {
            uint32_t kx = (uint32_t)ks << 5;
            uint32_t a[4][4];
            #pragma unroll
            for (int mt = 0; mt < 4; mt++) ldsm4(a[mt], ab + (aoff[mt] ^ kx));
            #pragma unroll
            for (int ng = 0; ng < 4; ng++) {
                uint32_t bq[4];
                ldsm4(bq, bb + (boff[ng] ^ kx));
                #pragma unroll
                for (int mt = 0; mt < 4; mt++) {
                    mma16816(d[mt][2 * ng],     a[mt], bq[0], bq[1]);
                    mma16816(d[mt][2 * ng + 1], a[mt], bq[2], bq[3]);
                }
            }
        }
    }
#undef LOADCHUNK

    // ---- epilogue ----
    int trow = lane >> 2, tcol = (lane & 3) * 2;
    #pragma unroll
    for (int mt = 0; mt < 4; mt++) {
        #pragma unroll
        for (int rr = 0; rr < 2; rr++) {
            size_t grow = (size_t)(m0 + warpM + mt * 16 + trow + rr * 8);
            #pragma unroll
            for (int nt = 0; nt < 8; nt++) {
                int gcol = n0 + warpN + nt * 8 + tcol;
                float v0 = d[mt][nt][rr * 2 + 0];
                float v1 = d[mt][nt][rr * 2 + 1];
                if (EPI == 1 || EPI == 3) {
                    float2 bq = *(const float2*)(bias + gcol);
                    float2 aq = *(const float2*)(addend + grow * N + gcol);
                    v0 = (v0 + bq.x + aq.x) * scale;
                    v1 = (v1 + bq.y + aq.y) * scale;
                } else {
                    v0 *= scale; v1 *= scale;
                }
                if (EPI <= 1) {
                    *(float2*)(Cf + grow * N + gcol) = make_float2(v0, v1);
                } else {
                    __nv_bfloat16* o = Cs + grow * (size_t)(2 * N) + gcol;
                    uint32_t hi = f2bf2(v0, v1);
                    uint32_t lo = f2bf2(v0 - bfround(v0), v1 - bfround(v1));
                    *(uint32_t*)(o)     = hi;
                    *(uint32_t*)(o + N) = lo;
                }
            }
        }
    }
}

// ===========================================================================
// softmax over S=1024, in place; also emits split [hi|lo] bf16 copy
// ===========================================================================
__global__ void softmax_split_kernel(float* __restrict__ attn,
                                     __nv_bfloat16* __restrict__ asp)
{
    size_t row = blockIdx.x;
    float* p = attn + row * 1024;
    int tid = threadIdx.x;

    float4 v = *(const float4*)&p[tid * 4];
    __shared__ float sm[8];

    float m = fmaxf(fmaxf(v.x, v.y), fmaxf(v.z, v.w));
    #pragma unroll
    for (int o = 16; o > 0; o >>= 1) m = fmaxf(m, __shfl_xor_sync(0xffffffffu, m, o));
    if ((tid & 31) == 0) sm[tid >> 5] = m;
    __syncthreads();
    float rmax = sm[0];
    #pragma unroll
    for (int w = 1; w < 8; w++) rmax = fmaxf(rmax, sm[w]);

    float e0 = expf(v.x - rmax), e1 = expf(v.y - rmax);
    float e2 = expf(v.z - rmax), e3 = expf(v.w - rmax);

    float s = (e0 + e1) + (e2 + e3);
    #pragma unroll
    for (int o = 16; o > 0; o >>= 1) s += __shfl_xor_sync(0xffffffffu, s, o);
    __syncthreads();
    if ((tid & 31) == 0) sm[tid >> 5] = s;
    __syncthreads();
    float rsum = 0.f;
    #pragma unroll
    for (int w = 0; w < 8; w++) rsum += sm[w];
    float inv = 1.f / rsum;

    float o0 = e0 * inv, o1 = e1 * inv, o2 = e2 * inv, o3 = e3 * inv;
    *(float4*)&p[tid * 4] = make_float4(o0, o1, o2, o3);

    uint32_t hi[2], lo[2];
    hi[0] = f2bf2(o0, o1);
    hi[1] = f2bf2(o2, o3);
    lo[0] = f2bf2(o0 - bfround(o0), o1 - bfround(o1));
    lo[1] = f2bf2(o2 - bfround(o2), o3 - bfround(o3));
    __nv_bfloat16* ob = asp + row * 2048 + tid * 4;
    *(uint2*)(ob)        = *(uint2*)hi;
    *(uint2*)(ob + 1024) = *(uint2*)lo;
}

// ===========================================================================
extern "C" void kernel_launch(void* const* d_in, const int* in_sizes, int n_in,
                              void* d_out, int out_size)
{
    const float* x     = (const float*)d_in[0];
    const float* te    = (const float*)d_in[1];
    const float* enc0  = (const float*)d_in[2];
    const float* enc1  = (const float*)d_in[3];
    const float* enc2  = (const float*)d_in[4];
    const float* in_v  = (const float*)d_in[5];
    const float* in_g  = (const float*)d_in[6];
    const float* in_b  = (const float*)d_in[7];
    const float* out_v = (const float*)d_in[8];
    const float* out_g = (const float*)d_in[9];
    const float* out_b = (const float*)d_in[10];

    float* out  = (float*)d_out;
    float* attn = out + (size_t)64 * 1024 * 512;

    __nv_bfloat16 *xsp, *hsp, *ctxsp, *attnsp, *esumT, *enc2T, *winsp, *woutsp;
    cudaGetSymbolAddress((void**)&xsp,    g_xsplit);
    cudaGetSymbolAddress((void**)&hsp,    g_hsplit);
    cudaGetSymbolAddress((void**)&ctxsp,  g_ctxsplit);
    cudaGetSymbolAddress((void**)&attnsp, g_attnsplit);
    cudaGetSymbolAddress((void**)&esumT,  g_esumT);
    cudaGetSymbolAddress((void**)&enc2T,  g_enc2T);
    cudaGetSymbolAddress((void**)&winsp,  g_winsplit);
    cudaGetSymbolAddress((void**)&woutsp, g_woutsplit);

    cudaFuncSetAttribute(mma_gemm<0,512>,  cudaFuncAttributeMaxDynamicSharedMemorySize, SMEM_BYTES);
    cudaFuncSetAttribute(mma_gemm<1,512>,  cudaFuncAttributeMaxDynamicSharedMemorySize, SMEM_BYTES);
    cudaFuncSetAttribute(mma_gemm<2,1024>, cudaFuncAttributeMaxDynamicSharedMemorySize, SMEM_BYTES);
    cudaFuncSetAttribute(mma_gemm<3,512>,  cudaFuncAttributeMaxDynamicSharedMemorySize, SMEM_BYTES);

    // ---- operand preparation ----
    wn_split_kernel<<<512, 256>>>(in_v,  in_g,  winsp,  512);
    wn_split_kernel<<<512, 256>>>(out_v, out_g, woutsp, 512);
    asplit_kernel<<<16384, 256>>>(x, xsp);
    // esumT: (enc0+enc1) [b,512,1024] -> [b,1024, 2*512]
    transpose_split_kernel<<<dim3(8, 32, 64), 256>>>(
        enc0, enc1, esumT, 512, 1024, (long long)512 * 1024, (long long)1024 * 1024);
    // enc2T: enc2 [b,1024,512] -> [b,512, 2*1024]
    transpose_split_kernel<<<dim3(16, 16, 64), 256>>>(
        enc2, nullptr, enc2T, 1024, 512, (long long)1024 * 512, (long long)512 * 2048);

    // K1: h = (x@Win^T + b + te)*sqrt(.5) -> hsplit   M=65536 N=512 KLOG=512
    mma_gemm<3,512><<<dim3(2, 512, 1), 256, SMEM_BYTES>>>(
        xsp, winsp, nullptr, hsp, 512, 0LL, 0LL, 0LL, in_b, te, SQRT_HALF_F);

    // K2: scores = h @ esum   per batch M=1024 N=1024 KLOG=512 -> attn (f32)
    mma_gemm<0,512><<<dim3(4, 8, 64), 256, SMEM_BYTES>>>(
        hsp, esumT, attn, nullptr, 1024,
        (long long)1024 * 1024, (long long)1024 * 1024, (long long)1024 * 1024,
        nullptr, nullptr, 1.0f);

    // K3: softmax + split
    softmax_split_kernel<<<65536, 256>>>(attn, attnsp);

    // K4: ctx = (attn @ enc2)*32 -> ctxsplit   per batch M=1024 N=512 KLOG=1024
    mma_gemm<2,1024><<<dim3(2, 8, 64), 256, SMEM_BYTES>>>(
        attnsp, enc2T, nullptr, ctxsp, 512,
        (long long)1024 * 2048, (long long)512 * 2048, (long long)1024 * 1024,
        nullptr, nullptr, 32.0f);

    // K5: out = (ctx@Wout^T + b + x)*sqrt(.5)  M=65536 N=512 KLOG=512 (f32)
    mma_gemm<1,512><<<dim3(2, 512, 1), 256, SMEM_BYTES>>>(
        ctxsp, woutsp, out, nullptr, 512, 0LL, 0LL, 0LL, out_b, x, SQRT_HALF_F);
}

// round 8
// speedup vs baseline: 1.0843x; 1.0843x over previous
#include <cuda_runtime.h>
#include <cuda_bf16.h>
#include <math.h>
#include <stdint.h>

// ===========================================================================
// AttentionLayer via mma.sync bf16 split GEMMs (fp32 accumulate in registers)
// B=64, T=1024, S=1024, C=E=512. Output = concat(out [B,T,C], attn [B,T,S])
//
// fp32 operand x split hi+lo bf16, stored [hi|lo] (2K columns). GEMM runs a
// 3-section logical K (sections remapped by the loader):
//   secs A: hi, lo, hi   secs B: hi, hi, lo
//   C = Ahi·Bhi + Alo·Bhi + Ahi·Blo  ≈ A·B  (err ~2^-18)
//
// R8: R5 GEMM core (128x128 CTA, m32n64 warps, 3-stage cp.async, 2 CTA/SM)
//     + two-stream fork/join overlap of prep + per-half softmax pipelining.
// ===========================================================================

static const float SQRT_HALF_F = 0.70710678118654752440f;

// ------------------------------ scratch ------------------------------------
__device__ __nv_bfloat16 g_xsplit  [(size_t)65536 * 1024];
__device__ __nv_bfloat16 g_hsplit  [(size_t)65536 * 1024];
__device__ __nv_bfloat16 g_ctxsplit[(size_t)65536 * 1024];
__device__ __nv_bfloat16 g_attnsplit[(size_t)65536 * 2048];
__device__ __nv_bfloat16 g_esumT   [(size_t)64 * 1024 * 1024];
__device__ __nv_bfloat16 g_enc2T   [(size_t)64 * 512 * 2048];
__device__ __nv_bfloat16 g_winsplit [512 * 1024];
__device__ __nv_bfloat16 g_woutsplit[512 * 1024];

// ------------------------------ helpers ------------------------------------
__device__ __forceinline__ uint32_t smem_u32(const void* p) {
    uint32_t a;
    asm("{ .reg .u64 t; cvta.to.shared.u64 t, %1; cvt.u32.u64 %0, t; }"
        : "=r"(a) : "l"(p));
    return a;
}

// pack two floats -> bf16x2 (first arg at lower address)
__device__ __forceinline__ uint32_t f2bf2(float lo, float hi) {
    uint32_t r;
    asm("cvt.rn.bf16x2.f32 %0, %1, %2;" : "=r"(r) : "f"(hi), "f"(lo));
    return r;
}
__device__ __forceinline__ float bfround(float v) {
    return __bfloat162float(__float2bfloat16(v));
}

__device__ __forceinline__ void cp16(uint32_t s, const void* g) {
    asm volatile("cp.async.cg.shared.global [%0], [%1], 16;" :: "r"(s), "l"(g));
}

__device__ __forceinline__ void ldsm4(uint32_t* r, uint32_t addr) {
    asm volatile("ldmatrix.sync.aligned.m8n8.x4.shared.b16 {%0,%1,%2,%3}, [%4];"
                 : "=r"(r[0]), "=r"(r[1]), "=r"(r[2]), "=r"(r[3]) : "r"(addr));
}

__device__ __forceinline__ void mma16816(float* d, const uint32_t* a,
                                         uint32_t b0, uint32_t b1) {
    asm volatile(
        "mma.sync.aligned.m16n8k16.row.col.f32.bf16.bf16.f32 "
        "{%0,%1,%2,%3}, {%4,%5,%6,%7}, {%8,%9}, {%0,%1,%2,%3};"
        : "+f"(d[0]), "+f"(d[1]), "+f"(d[2]), "+f"(d[3])
        : "r"(a[0]), "r"(a[1]), "r"(a[2]), "r"(a[3]), "r"(b0), "r"(b1));
}

// ===========================================================================
// weight-norm + split [hi|lo]: one block per row, cols=512
// ===========================================================================
__global__ void wn_split_kernel(const float* __restrict__ v, const float* __restrict__ g,
                                __nv_bfloat16* __restrict__ w, int cols)
{
    int r = blockIdx.x;
    int tid = threadIdx.x;
    const float* vr = v + (size_t)r * cols;

    float ss = 0.f;
    for (int c = tid; c < cols; c += blockDim.x) { float t = vr[c]; ss += t * t; }
    __shared__ float sm[32];
    #pragma unroll
    for (int o = 16; o > 0; o >>= 1) ss += __shfl_down_sync(0xffffffffu, ss, o);
    int warp = tid >> 5, lane = tid & 31;
    if (lane == 0) sm[warp] = ss;
    __syncthreads();
    int nw = blockDim.x >> 5;
    if (warp == 0) {
        float s2 = (lane < nw) ? sm[lane] : 0.f;
        #pragma unroll
        for (int o = 16; o > 0; o >>= 1) s2 += __shfl_down_sync(0xffffffffu, s2, o);
        if (lane == 0) sm[0] = s2;
    }
    __syncthreads();
    float scale = g[r] / sqrtf(sm[0]);
    __nv_bfloat16* wr = w + (size_t)r * (2 * cols);
    for (int c = tid; c < cols; c += blockDim.x) {
        float wv = vr[c] * scale;
        __nv_bfloat16 h = __float2bfloat16(wv);
        __nv_bfloat16 l = __float2bfloat16(wv - __bfloat162float(h));
        wr[c] = h;
        wr[cols + c] = l;
    }
}

// ===========================================================================
// A-split [hi|lo]:  x [65536,512] -> [65536,1024]
// ===========================================================================
__global__ void asplit_kernel(const float* __restrict__ in, __nv_bfloat16* __restrict__ out)
{
    size_t idx = (size_t)blockIdx.x * 256 + threadIdx.x;
    size_t row = idx >> 6;
    int g = (int)(idx & 63);
    const float* p = in + row * 512 + g * 8;
    float4 f0 = *(const float4*)p;
    float4 f1 = *(const float4*)(p + 4);
    float v[8] = {f0.x, f0.y, f0.z, f0.w, f1.x, f1.y, f1.z, f1.w};
    uint32_t hi[4], lo[4];
    #pragma unroll
    for (int q = 0; q < 4; q++) {
        hi[q] = f2bf2(v[2*q], v[2*q+1]);
        lo[q] = f2bf2(v[2*q] - bfround(v[2*q]), v[2*q+1] - bfround(v[2*q+1]));
    }
    __nv_bfloat16* o = out + row * 1024 + g * 8;
    *(uint4*)(o)       = *(uint4*)hi;
    *(uint4*)(o + 512) = *(uint4*)lo;
}

// ===========================================================================
// transpose + split [hi|lo]: in (optionally in0+in1) [R, Cc] -> out [Cc, 2R]
// ===========================================================================
__global__ void transpose_split_kernel(const float* __restrict__ in0,
                                       const float* __restrict__ in1,
                                       __nv_bfloat16* __restrict__ out,
                                       int R, int Cc, long long sIn, long long sOut)
{
    __shared__ float tile[64][33];
    int b = blockIdx.z;
    const float* A0 = in0 + (size_t)b * sIn;
    const float* A1 = in1 ? in1 + (size_t)b * sIn : nullptr;
    __nv_bfloat16* O = out + (size_t)b * sOut;
    int r0 = blockIdx.x * 64;
    int c0 = blockIdx.y * 32;
    int tid = threadIdx.x;

    #pragma unroll
    for (int i = 0; i < 8; i++) {
        int idx = i * 256 + tid;
        int rr = idx >> 5, cc = idx & 31;
        size_t off = (size_t)(r0 + rr) * Cc + c0 + cc;
        float vv = A0[off];
        if (A1) vv += A1[off];
        tile[rr][cc] = vv;
    }
    __syncthreads();

    int j = tid >> 3;
    int g = tid & 7;
    float v[8];
    #pragma unroll
    for (int u = 0; u < 8; u++) v[u] = tile[g * 8 + u][j];
    uint32_t hi[4], lo[4];
    #pragma unroll
    for (int p = 0; p < 4; p++) {
        hi[p] = f2bf2(v[2*p], v[2*p+1]);
        lo[p] = f2bf2(v[2*p] - bfround(v[2*p]), v[2*p+1] - bfround(v[2*p+1]));
    }
    __nv_bfloat16* ob = O + (size_t)(c0 + j) * (2 * R) + r0 + g * 8;
    *(uint4*)(ob)     = *(uint4*)hi;
    *(uint4*)(ob + R) = *(uint4*)lo;
}

// ===========================================================================
// mma.sync GEMM: C[128x128] = A x B^T over 3 remapped K-sections, fp32 accum.
// A stored [M, 2*KLOG] as [hi|lo]; B stored [N, 2*KLOG] as [hi|lo].
// Section maps: A {hi,lo,hi}, B {hi,hi,lo}. 3-stage cp.async pipeline.
// EPI: 0 = f32 C=acc*scale ; 1 = f32 C=(acc+bias+addend)*scale
//      2 = split [hi|lo] C=acc*scale ; 3 = split (acc+bias+addend)*scale
// ===========================================================================
#define SMEM_BYTES 98304

template <int EPI, int KLOG>
__global__ __launch_bounds__(256, 2)
void mma_gemm(const __nv_bfloat16* __restrict__ A,
              const __nv_bfloat16* __restrict__ B,
              float* __restrict__ Cf, __nv_bfloat16* __restrict__ Cs,
              int N,
              long long sA, long long sB, long long sC,
              const float* __restrict__ bias,
              const float* __restrict__ addend,
              float scale)
{
    constexpr int K2E    = 2 * KLOG;       // stored row length (elements)
    constexpr int SECLEN = KLOG / 64;      // chunks per section
    constexpr int NUMK   = 3 * SECLEN;

    extern __shared__ __align__(1024) char smem[];
    uint32_t sbase = smem_u32(smem);
    const uint32_t st0 = sbase, st1 = sbase + 32768, st2 = sbase + 65536;

    int tid = threadIdx.x, wid = tid >> 5, lane = tid & 31;
    int z = blockIdx.z;
    A += (size_t)z * sA;
    B += (size_t)z * sB;
    if (EPI <= 1) Cf += (size_t)z * sC; else Cs += (size_t)z * sC;
    int m0 = blockIdx.y * 128, n0 = blockIdx.x * 128;
    int warpM = (wid >> 1) * 32, warpN = (wid & 1) * 64;

    // ---- loader mapping: 4x16B cp.async per operand per chunk ----
    int c = tid & 7, rbase = tid >> 3;
    const size_t rs = (size_t)32 * K2E * 2;   // 32 rows in bytes
    const char* aRow = (const char*)(A + (size_t)(m0 + rbase) * K2E + c * 8);
    const char* bRow = (const char*)(B + (size_t)(n0 + rbase) * K2E + c * 8);
    uint32_t swo[4];
    #pragma unroll
    for (int i = 0; i < 4; i++) {
        uint32_t bo = (uint32_t)(rbase + 32 * i) * 128 + c * 16;
        swo[i] = bo ^ ((bo >> 3) & 0x70);
    }

    // per-chunk byte offsets via section remap
    auto koffA = [](int ck) -> size_t {
        int sec = ck / SECLEN;
        int kk  = ck - sec * SECLEN;
        int map = (sec == 1) ? 1 : 0;          // A: hi, lo, hi
        return ((size_t)map * KLOG + (size_t)kk * 64) * 2;
    };
    auto koffB = [](int ck) -> size_t {
        int sec = ck / SECLEN;
        int kk  = ck - sec * SECLEN;
        int map = (sec == 2) ? 1 : 0;          // B: hi, hi, lo
        return ((size_t)map * KLOG + (size_t)kk * 64) * 2;
    };

#define LOADCHUNK(STG, CK) do {                                            \
        size_t oa_ = koffA(CK), ob_ = koffB(CK);                           \
        uint32_t ab_ = (STG), bb_ = (STG) + 16384;                         \
        cp16(ab_ + swo[0], aRow + oa_);                                    \
        cp16(ab_ + swo[1], aRow + oa_ + rs);                               \
        cp16(ab_ + swo[2], aRow + oa_ + 2 * rs);                           \
        cp16(ab_ + swo[3], aRow + oa_ + 3 * rs);                           \
        cp16(bb_ + swo[0], bRow + ob_);                                    \
        cp16(bb_ + swo[1], bRow + ob_ + rs);                               \
        cp16(bb_ + swo[2], bRow + ob_ + 2 * rs);                           \
        cp16(bb_ + swo[3], bRow + ob_ + 3 * rs);                           \
        asm volatile("cp.async.commit_group;" ::: "memory");               \
    } while (0)

    // ---- ldmatrix per-lane swizzled offsets ----
    uint32_t aoff[2], boff[4];
    {
        int l = lane;
        #pragma unroll
        for (int mt = 0; mt < 2; mt++) {
            int row = warpM + mt * 16 + (l & 15);
            uint32_t cb = (uint32_t)((l >> 4) << 4);
            aoff[mt] = (uint32_t)row * 128 + (cb ^ (((uint32_t)row & 7) << 4));
        }
        #pragma unroll
        for (int ng = 0; ng < 4; ng++) {
            int row = warpN + ng * 16 + (l & 7) + ((l >> 4) << 3);
            uint32_t cb = (uint32_t)(((l >> 3) & 1) << 4);
            boff[ng] = (uint32_t)row * 128 + (cb ^ (((uint32_t)row & 7) << 4));
        }
    }

    float d[2][8][4];
    #pragma unroll
    for (int mt = 0; mt < 2; mt++)
        #pragma unroll
        for (int nt = 0; nt < 8; nt++)
            #pragma unroll
            for (int q = 0; q < 4; q++) d[mt][nt][q] = 0.f;

    // prologue: chunks 0,1 into stages 0,1
    LOADCHUNK(st0, 0);
    LOADCHUNK(st1, 1);

    uint32_t stage[3] = { st0, st1, st2 };
    int cur = 0, nxt = 2;   // stage index for compute / for next load

    for (int ck = 0; ck < NUMK; ck++) {
        if (ck < NUMK - 1) asm volatile("cp.async.wait_group 1;" ::: "memory");
        else               asm volatile("cp.async.wait_group 0;" ::: "memory");
        __syncthreads();

        if (ck + 2 < NUMK) {
            LOADCHUNK(stage[nxt], ck + 2);
            nxt = (nxt == 2) ? 0 : nxt + 1;
        }

        uint32_t ab = stage[cur], bb = stage[cur] + 16384;
        cur = (cur == 2) ? 0 : cur + 1;
        #pragma unroll
        for (int ks = 0; ks < 4; ks++) {
            uint32_t kx = (uint32_t)ks << 5;
            uint32_t a[2][4];
            ldsm4(a[0], ab + (aoff[0] ^ kx));
            ldsm4(a[1], ab + (aoff[1] ^ kx));
            #pragma unroll
            for (int ng = 0; ng < 4; ng++) {
                uint32_t bq[4];
                ldsm4(bq, bb + (boff[ng] ^ kx));
                #pragma unroll
                for (int mt = 0; mt < 2; mt++) {
                    mma16816(d[mt][2 * ng],     a[mt], bq[0], bq[1]);
                    mma16816(d[mt][2 * ng + 1], a[mt], bq[2], bq[3]);
                }
            }
        }
    }
#undef LOADCHUNK

    // ---- epilogue ----
    int trow = lane >> 2, tcol = (lane & 3) * 2;
    #pragma unroll
    for (int mt = 0; mt < 2; mt++) {
        #pragma unroll
        for (int rr = 0; rr < 2; rr++) {
            size_t grow = (size_t)(m0 + warpM + mt * 16 + trow + rr * 8);
            #pragma unroll
            for (int nt = 0; nt < 8; nt++) {
                int gcol = n0 + warpN + nt * 8 + tcol;
                float v0 = d[mt][nt][rr * 2 + 0];
                float v1 = d[mt][nt][rr * 2 + 1];
                if (EPI == 1 || EPI == 3) {
                    float2 bq = *(const float2*)(bias + gcol);
                    float2 aq = *(const float2*)(addend + grow * N + gcol);
                    v0 = (v0 + bq.x + aq.x) * scale;
                    v1 = (v1 + bq.y + aq.y) * scale;
                } else {
                    v0 *= scale; v1 *= scale;
                }
                if (EPI <= 1) {
                    *(float2*)(Cf + grow * N + gcol) = make_float2(v0, v1);
                } else {
                    __nv_bfloat16* o = Cs + grow * (size_t)(2 * N) + gcol;
                    uint32_t hi = f2bf2(v0, v1);
                    uint32_t lo = f2bf2(v0 - bfround(v0), v1 - bfround(v1));
                    *(uint32_t*)(o)     = hi;
                    *(uint32_t*)(o + N) = lo;
                }
            }
        }
    }
}

// ===========================================================================
// softmax over S=1024, in place; also emits split [hi|lo] bf16 copy
// ===========================================================================
__global__ void softmax_split_kernel(float* __restrict__ attn,
                                     __nv_bfloat16* __restrict__ asp)
{
    size_t row = blockIdx.x;
    float* p = attn + row * 1024;
    int tid = threadIdx.x;

    float4 v = *(const float4*)&p[tid * 4];
    __shared__ float sm[8];

    float m = fmaxf(fmaxf(v.x, v.y), fmaxf(v.z, v.w));
    #pragma unroll
    for (int o = 16; o > 0; o >>= 1) m = fmaxf(m, __shfl_xor_sync(0xffffffffu, m, o));
    if ((tid & 31) == 0) sm[tid >> 5] = m;
    __syncthreads();
    float rmax = sm[0];
    #pragma unroll
    for (int w = 1; w < 8; w++) rmax = fmaxf(rmax, sm[w]);

    float e0 = expf(v.x - rmax), e1 = expf(v.y - rmax);
    float e2 = expf(v.z - rmax), e3 = expf(v.w - rmax);

    float s = (e0 + e1) + (e2 + e3);
    #pragma unroll
    for (int o = 16; o > 0; o >>= 1) s += __shfl_xor_sync(0xffffffffu, s, o);
    __syncthreads();
    if ((tid & 31) == 0) sm[tid >> 5] = s;
    __syncthreads();
    float rsum = 0.f;
    #pragma unroll
    for (int w = 0; w < 8; w++) rsum += sm[w];
    float inv = 1.f / rsum;

    float o0 = e0 * inv, o1 = e1 * inv, o2 = e2 * inv, o3 = e3 * inv;
    *(float4*)&p[tid * 4] = make_float4(o0, o1, o2, o3);

    uint32_t hi[2], lo[2];
    hi[0] = f2bf2(o0, o1);
    hi[1] = f2bf2(o2, o3);
    lo[0] = f2bf2(o0 - bfround(o0), o1 - bfround(o1));
    lo[1] = f2bf2(o2 - bfround(o2), o3 - bfround(o3));
    __nv_bfloat16* ob = asp + row * 2048 + tid * 4;
    *(uint2*)(ob)        = *(uint2*)hi;
    *(uint2*)(ob + 1024) = *(uint2*)lo;
}

// ===========================================================================
extern "C" void kernel_launch(void* const* d_in, const int* in_sizes, int n_in,
                              void* d_out, int out_size)
{
    const float* x     = (const float*)d_in[0];
    const float* te    = (const float*)d_in[1];
    const float* enc0  = (const float*)d_in[2];
    const float* enc1  = (const float*)d_in[3];
    const float* enc2  = (const float*)d_in[4];
    const float* in_v  = (const float*)d_in[5];
    const float* in_g  = (const float*)d_in[6];
    const float* in_b  = (const float*)d_in[7];
    const float* out_v = (const float*)d_in[8];
    const float* out_g = (const float*)d_in[9];
    const float* out_b = (const float*)d_in[10];

    float* out  = (float*)d_out;
    float* attn = out + (size_t)64 * 1024 * 512;

    __nv_bfloat16 *xsp, *hsp, *ctxsp, *attnsp, *esumT, *enc2T, *winsp, *woutsp;
    cudaGetSymbolAddress((void**)&xsp,    g_xsplit);
    cudaGetSymbolAddress((void**)&hsp,    g_hsplit);
    cudaGetSymbolAddress((void**)&ctxsp,  g_ctxsplit);
    cudaGetSymbolAddress((void**)&attnsp, g_attnsplit);
    cudaGetSymbolAddress((void**)&esumT,  g_esumT);
    cudaGetSymbolAddress((void**)&enc2T,  g_enc2T);
    cudaGetSymbolAddress((void**)&winsp,  g_winsplit);
    cudaGetSymbolAddress((void**)&woutsp, g_woutsplit);

    cudaFuncSetAttribute(mma_gemm<0,512>,  cudaFuncAttributeMaxDynamicSharedMemorySize, SMEM_BYTES);
    cudaFuncSetAttribute(mma_gemm<1,512>,  cudaFuncAttributeMaxDynamicSharedMemorySize, SMEM_BYTES);
    cudaFuncSetAttribute(mma_gemm<2,1024>, cudaFuncAttributeMaxDynamicSharedMemorySize, SMEM_BYTES);
    cudaFuncSetAttribute(mma_gemm<3,512>,  cudaFuncAttributeMaxDynamicSharedMemorySize, SMEM_BYTES);

    // side stream + events for fork/join inside graph capture (host-side
    // objects only; created per call — capture/correctness calls are rare)
    cudaStream_t s1;
    cudaStreamCreateWithFlags(&s1, cudaStreamNonBlocking);
    cudaEvent_t eFork, ePrep, eK1, eHalfB;
    cudaEventCreateWithFlags(&eFork,  cudaEventDisableTiming);
    cudaEventCreateWithFlags(&ePrep,  cudaEventDisableTiming);
    cudaEventCreateWithFlags(&eK1,    cudaEventDisableTiming);
    cudaEventCreateWithFlags(&eHalfB, cudaEventDisableTiming);

    // ---- fork ----
    cudaEventRecord(eFork, 0);
    cudaStreamWaitEvent(s1, eFork, 0);

    // side stream: B-operand prep for K2/K4/K5
    wn_split_kernel<<<512, 256, 0, s1>>>(out_v, out_g, woutsp, 512);
    transpose_split_kernel<<<dim3(8, 32, 64), 256, 0, s1>>>(
        enc0, enc1, esumT, 512, 1024, (long long)512 * 1024, (long long)1024 * 1024);
    transpose_split_kernel<<<dim3(16, 16, 64), 256, 0, s1>>>(
        enc2, nullptr, enc2T, 1024, 512, (long long)1024 * 512, (long long)512 * 2048);
    cudaEventRecord(ePrep, s1);

    // main stream: K1 chain
    wn_split_kernel<<<512, 256>>>(in_v, in_g, winsp, 512);
    asplit_kernel<<<16384, 256>>>(x, xsp);
    mma_gemm<3,512><<<dim3(4, 512, 1), 256, SMEM_BYTES>>>(
        xsp, winsp, nullptr, hsp, 512, 0LL, 0LL, 0LL, in_b, te, SQRT_HALF_F);

    // join: main needs esumT before K2; record K1-done for side stream
    cudaStreamWaitEvent(0, ePrep, 0);
    cudaEventRecord(eK1, 0);
    cudaStreamWaitEvent(s1, eK1, 0);

    // ---- half-pipelined K2 -> softmax -> K4 (batches 0-31 main, 32-63 side)
    const long long sA2 = (long long)1024 * 1024;   // hsp per-batch
    const long long sB2 = (long long)1024 * 1024;   // esumT per-batch
    const long long sC2 = (long long)1024 * 1024;   // attn per-batch
    const long long sA4 = (long long)1024 * 2048;   // attnsp per-batch
    const long long sB4 = (long long)512 * 2048;    // enc2T per-batch
    const long long sC4 = (long long)1024 * 1024;   // ctxsp per-batch
    const size_t ho = (size_t)32 * sA2;             // half offsets
    const size_t eo = (size_t)32 * sB2;
    const size_t ao = (size_t)32 * sC2;
    const size_t aso = (size_t)32 * sA4;
    const size_t e2o = (size_t)32 * sB4;
    const size_t co  = (size_t)32 * sC4;

    // main: half A
    mma_gemm<0,512><<<dim3(8, 8, 32), 256, SMEM_BYTES>>>(
        hsp, esumT, attn, nullptr, 1024, sA2, sB2, sC2, nullptr, nullptr, 1.0f);
    softmax_split_kernel<<<32768, 256>>>(attn, attnsp);
    mma_gemm<2,1024><<<dim3(4, 8, 32), 256, SMEM_BYTES>>>(
        attnsp, enc2T, nullptr, ctxsp, 512, sA4, sB4, sC4, nullptr, nullptr, 32.0f);

    // side: half B
    mma_gemm<0,512><<<dim3(8, 8, 32), 256, SMEM_BYTES, s1>>>(
        hsp + ho, esumT + eo, attn + ao, nullptr, 1024, sA2, sB2, sC2,
        nullptr, nullptr, 1.0f);
    softmax_split_kernel<<<32768, 256, 0, s1>>>(attn + ao, attnsp + aso);
    mma_gemm<2,1024><<<dim3(4, 8, 32), 256, SMEM_BYTES, s1>>>(
        attnsp + aso, enc2T + e2o, nullptr, ctxsp + co, 512, sA4, sB4, sC4,
        nullptr, nullptr, 32.0f);
    cudaEventRecord(eHalfB, s1);

    // join before K5 (needs full ctxsp + woutsp)
    cudaStreamWaitEvent(0, eHalfB, 0);

    // K5: out = (ctx@Wout^T + b + x)*sqrt(.5)  M=65536 N=512 KLOG=512 (f32)
    mma_gemm<1,512><<<dim3(4, 512, 1), 256, SMEM_BYTES>>>(
        ctxsp, woutsp, out, nullptr, 512, 0LL, 0LL, 0LL, out_b, x, SQRT_HALF_F);
}

// round 9
// speedup vs baseline: 1.2801x; 1.1806x over previous
#include <cuda_runtime.h>
#include <cuda_bf16.h>
#include <cuda_fp16.h>
#include <math.h>
#include <stdint.h>

// ===========================================================================
// AttentionLayer via mma.sync split GEMMs (fp32 accumulate in registers)
// B=64, T=1024, S=1024, C=E=512. Output = concat(out [B,T,C], attn [B,T,S])
//
// K1 (h = x@Win^T+b+te)  : 3-term bf16 split (scores amplify h errors)
// K2 (scores = h@esum)   : 3-term bf16 split
// K4 (ctx = attn@enc2)   : 2-term fp16: attn_f16·(enc2_hi + enc2_lo)
// K5 (out = ctx@Wout^T+.): 2-term fp16: ctx_f16·(W_hi + W_lo)
// ===========================================================================

static const float SQRT_HALF_F = 0.70710678118654752440f;

// ------------------------------ scratch ------------------------------------
__device__ __nv_bfloat16 g_xsplit  [(size_t)65536 * 1024];
__device__ __nv_bfloat16 g_hsplit  [(size_t)65536 * 1024];
__device__ __half        g_ctx_f16 [(size_t)65536 * 512];
__device__ __half        g_attn_f16[(size_t)65536 * 1024];
__device__ __nv_bfloat16 g_esumT   [(size_t)64 * 1024 * 1024];
__device__ __half        g_enc2T   [(size_t)64 * 512 * 2048];
__device__ __nv_bfloat16 g_winsplit [512 * 1024];
__device__ __half        g_woutsplit[512 * 1024];

// ------------------------------ helpers ------------------------------------
__device__ __forceinline__ uint32_t smem_u32(const void* p) {
    uint32_t a;
    asm("{ .reg .u64 t; cvta.to.shared.u64 t, %1; cvt.u32.u64 %0, t; }"
        : "=r"(a) : "l"(p));
    return a;
}

// pack two floats -> bf16x2 / f16x2 (first arg at lower address)
__device__ __forceinline__ uint32_t f2bf2(float lo, float hi) {
    uint32_t r;
    asm("cvt.rn.bf16x2.f32 %0, %1, %2;" : "=r"(r) : "f"(hi), "f"(lo));
    return r;
}
__device__ __forceinline__ uint32_t f2h2(float lo, float hi) {
    uint32_t r;
    asm("cvt.rn.f16x2.f32 %0, %1, %2;" : "=r"(r) : "f"(hi), "f"(lo));
    return r;
}
__device__ __forceinline__ float bfround(float v) {
    return __bfloat162float(__float2bfloat16(v));
}
__device__ __forceinline__ float hround(float v) {
    return __half2float(__float2half_rn(v));
}

__device__ __forceinline__ void cp16(uint32_t s, const void* g) {
    asm volatile("cp.async.cg.shared.global [%0], [%1], 16;" :: "r"(s), "l"(g));
}

__device__ __forceinline__ void ldsm4(uint32_t* r, uint32_t addr) {
    asm volatile("ldmatrix.sync.aligned.m8n8.x4.shared.b16 {%0,%1,%2,%3}, [%4];"
                 : "=r"(r[0]), "=r"(r[1]), "=r"(r[2]), "=r"(r[3]) : "r"(addr));
}

template <bool HALF>
__device__ __forceinline__ void mma16816(float* d, const uint32_t* a,
                                         uint32_t b0, uint32_t b1) {
    if (HALF)
        asm volatile(
            "mma.sync.aligned.m16n8k16.row.col.f32.f16.f16.f32 "
            "{%0,%1,%2,%3}, {%4,%5,%6,%7}, {%8,%9}, {%0,%1,%2,%3};"
            : "+f"(d[0]), "+f"(d[1]), "+f"(d[2]), "+f"(d[3])
            : "r"(a[0]), "r"(a[1]), "r"(a[2]), "r"(a[3]), "r"(b0), "r"(b1));
    else
        asm volatile(
            "mma.sync.aligned.m16n8k16.row.col.f32.bf16.bf16.f32 "
            "{%0,%1,%2,%3}, {%4,%5,%6,%7}, {%8,%9}, {%0,%1,%2,%3};"
            : "+f"(d[0]), "+f"(d[1]), "+f"(d[2]), "+f"(d[3])
            : "r"(a[0]), "r"(a[1]), "r"(a[2]), "r"(a[3]), "r"(b0), "r"(b1));
}

// ===========================================================================
// weight-norm + split [hi|lo] bf16: one block per row, cols=512
// ===========================================================================
__global__ void wn_split_kernel(const float* __restrict__ v, const float* __restrict__ g,
                                __nv_bfloat16* __restrict__ w, int cols)
{
    int r = blockIdx.x;
    int tid = threadIdx.x;
    const float* vr = v + (size_t)r * cols;

    float ss = 0.f;
    for (int c = tid; c < cols; c += blockDim.x) { float t = vr[c]; ss += t * t; }
    __shared__ float sm[32];
    #pragma unroll
    for (int o = 16; o > 0; o >>= 1) ss += __shfl_down_sync(0xffffffffu, ss, o);
    int warp = tid >> 5, lane = tid & 31;
    if (lane == 0) sm[warp] = ss;
    __syncthreads();
    int nw = blockDim.x >> 5;
    if (warp == 0) {
        float s2 = (lane < nw) ? sm[lane] : 0.f;
        #pragma unroll
        for (int o = 16; o > 0; o >>= 1) s2 += __shfl_down_sync(0xffffffffu, s2, o);
        if (lane == 0) sm[0] = s2;
    }
    __syncthreads();
    float scale = g[r] / sqrtf(sm[0]);
    __nv_bfloat16* wr = w + (size_t)r * (2 * cols);
    for (int c = tid; c < cols; c += blockDim.x) {
        float wv = vr[c] * scale;
        __nv_bfloat16 h = __float2bfloat16(wv);
        __nv_bfloat16 l = __float2bfloat16(wv - __bfloat162float(h));
        wr[c] = h;
        wr[cols + c] = l;
    }
}

// ===========================================================================
// weight-norm + split [hi|lo] fp16 (for W_out): one block per row
// ===========================================================================
__global__ void wn_split_f16_kernel(const float* __restrict__ v, const float* __restrict__ g,
                                    __half* __restrict__ w, int cols)
{
    int r = blockIdx.x;
    int tid = threadIdx.x;
    const float* vr = v + (size_t)r * cols;

    float ss = 0.f;
    for (int c = tid; c < cols; c += blockDim.x) { float t = vr[c]; ss += t * t; }
    __shared__ float sm[32];
    #pragma unroll
    for (int o = 16; o > 0; o >>= 1) ss += __shfl_down_sync(0xffffffffu, ss, o);
    int warp = tid >> 5, lane = tid & 31;
    if (lane == 0) sm[warp] = ss;
    __syncthreads();
    int nw = blockDim.x >> 5;
    if (warp == 0) {
        float s2 = (lane < nw) ? sm[lane] : 0.f;
        #pragma unroll
        for (int o = 16; o > 0; o >>= 1) s2 += __shfl_down_sync(0xffffffffu, s2, o);
        if (lane == 0) sm[0] = s2;
    }
    __syncthreads();
    float scale = g[r] / sqrtf(sm[0]);
    __half* wr = w + (size_t)r * (2 * cols);
    for (int c = tid; c < cols; c += blockDim.x) {
        float wv = vr[c] * scale;
        __half h = __float2half_rn(wv);
        __half l = __float2half_rn(wv - __half2float(h));
        wr[c] = h;
        wr[cols + c] = l;
    }
}

// ===========================================================================
// A-split [hi|lo] bf16:  x [65536,512] -> [65536,1024]
// ===========================================================================
__global__ void asplit_kernel(const float* __restrict__ in, __nv_bfloat16* __restrict__ out)
{
    size_t idx = (size_t)blockIdx.x * 256 + threadIdx.x;
    size_t row = idx >> 6;
    int g = (int)(idx & 63);
    const float* p = in + row * 512 + g * 8;
    float4 f0 = *(const float4*)p;
    float4 f1 = *(const float4*)(p + 4);
    float v[8] = {f0.x, f0.y, f0.z, f0.w, f1.x, f1.y, f1.z, f1.w};
    uint32_t hi[4], lo[4];
    #pragma unroll
    for (int q = 0; q < 4; q++) {
        hi[q] = f2bf2(v[2*q], v[2*q+1]);
        lo[q] = f2bf2(v[2*q] - bfround(v[2*q]), v[2*q+1] - bfround(v[2*q+1]));
    }
    __nv_bfloat16* o = out + row * 1024 + g * 8;
    *(uint4*)(o)       = *(uint4*)hi;
    *(uint4*)(o + 512) = *(uint4*)lo;
}

// ===========================================================================
// transpose + split [hi|lo] bf16: in0(+in1) [R, Cc] per batch -> out [Cc, 2R]
// ===========================================================================
__global__ void transpose_split_kernel(const float* __restrict__ in0,
                                       const float* __restrict__ in1,
                                       __nv_bfloat16* __restrict__ out,
                                       int R, int Cc, long long sIn, long long sOut)
{
    __shared__ float tile[64][33];
    int b = blockIdx.z;
    const float* A0 = in0 + (size_t)b * sIn;
    const float* A1 = in1 ? in1 + (size_t)b * sIn : nullptr;
    __nv_bfloat16* O = out + (size_t)b * sOut;
    int r0 = blockIdx.x * 64;
    int c0 = blockIdx.y * 32;
    int tid = threadIdx.x;

    #pragma unroll
    for (int i = 0; i < 8; i++) {
        int idx = i * 256 + tid;
        int rr = idx >> 5, cc = idx & 31;
        size_t off = (size_t)(r0 + rr) * Cc + c0 + cc;
        float vv = A0[off];
        if (A1) vv += A1[off];
        tile[rr][cc] = vv;
    }
    __syncthreads();

    int j = tid >> 3;
    int g = tid & 7;
    float v[8];
    #pragma unroll
    for (int u = 0; u < 8; u++) v[u] = tile[g * 8 + u][j];
    uint32_t hi[4], lo[4];
    #pragma unroll
    for (int p = 0; p < 4; p++) {
        hi[p] = f2bf2(v[2*p], v[2*p+1]);
        lo[p] = f2bf2(v[2*p] - bfround(v[2*p]), v[2*p+1] - bfround(v[2*p+1]));
    }
    __nv_bfloat16* ob = O + (size_t)(c0 + j) * (2 * R) + r0 + g * 8;
    *(uint4*)(ob)     = *(uint4*)hi;
    *(uint4*)(ob + R) = *(uint4*)lo;
}

// ===========================================================================
// transpose + split [hi|lo] fp16: enc2 [R, Cc] per batch -> out [Cc, 2R]
// ===========================================================================
__global__ void transpose_split_f16_kernel(const float* __restrict__ in0,
                                           __half* __restrict__ out,
                                           int R, int Cc, long long sIn, long long sOut)
{
    __shared__ float tile[64][33];
    int b = blockIdx.z;
    const float* A0 = in0 + (size_t)b * sIn;
    __half* O = out + (size_t)b * sOut;
    int r0 = blockIdx.x * 64;
    int c0 = blockIdx.y * 32;
    int tid = threadIdx.x;

    #pragma unroll
    for (int i = 0; i < 8; i++) {
        int idx = i * 256 + tid;
        int rr = idx >> 5, cc = idx & 31;
        tile[rr][cc] = A0[(size_t)(r0 + rr) * Cc + c0 + cc];
    }
    __syncthreads();

    int j = tid >> 3;
    int g = tid & 7;
    float v[8];
    #pragma unroll
    for (int u = 0; u < 8; u++) v[u] = tile[g * 8 + u][j];
    uint32_t hi[4], lo[4];
    #pragma unroll
    for (int p = 0; p < 4; p++) {
        hi[p] = f2h2(v[2*p], v[2*p+1]);
        lo[p] = f2h2(v[2*p] - hround(v[2*p]), v[2*p+1] - hround(v[2*p+1]));
    }
    __half* ob = O + (size_t)(c0 + j) * (2 * R) + r0 + g * 8;
    *(uint4*)(ob)     = *(uint4*)hi;
    *(uint4*)(ob + R) = *(uint4*)lo;
}

// ===========================================================================
// mma.sync GEMM: C[128x128] = A x B^T over NSEC remapped K-sections.
// A row length AROW elems; B row length BROW. Section s uses +KLOG offset
// iff (AMAP>>s)&1 (resp BMAP). bf16 or fp16 operands per HALF.
// EPI: 0 = f32 C=acc*scale ; 1 = f32 C=(acc+bias+addend)*scale
//      3 = bf16 split [hi|lo] (acc+bias+addend)*scale ; 4 = fp16 single, *scale
// ===========================================================================
#define SMEM_BYTES 98304

template <int EPI, int KLOG, int NSEC, int AMAP, int BMAP, int AROW, int BROW, bool HALF>
__global__ __launch_bounds__(256, 2)
void mma_gemm(const uint16_t* __restrict__ A,
              const uint16_t* __restrict__ B,
              float* __restrict__ Cf, void* __restrict__ Cs,
              int N,
              long long sA, long long sB, long long sC,
              const float* __restrict__ bias,
              const float* __restrict__ addend,
              float scale)
{
    constexpr int SECLEN = KLOG / 64;      // chunks per section
    constexpr int NUMK   = NSEC * SECLEN;

    extern __shared__ __align__(1024) char smem[];
    uint32_t sbase = smem_u32(smem);
    const uint32_t st0 = sbase, st1 = sbase + 32768, st2 = sbase + 65536;

    int tid = threadIdx.x, wid = tid >> 5, lane = tid & 31;
    int z = blockIdx.z;
    A += (size_t)z * sA;
    B += (size_t)z * sB;
    int m0 = blockIdx.y * 128, n0 = blockIdx.x * 128;
    int warpM = (wid >> 1) * 32, warpN = (wid & 1) * 64;

    // ---- loader mapping: 4x16B cp.async per operand per chunk ----
    int c = tid & 7, rbase = tid >> 3;
    const size_t rsA = (size_t)32 * AROW * 2;   // 32 rows in bytes
    const size_t rsB = (size_t)32 * BROW * 2;
    const char* aRow = (const char*)(A + (size_t)(m0 + rbase) * AROW + c * 8);
    const char* bRow = (const char*)(B + (size_t)(n0 + rbase) * BROW + c * 8);
    uint32_t swo[4];
    #pragma unroll
    for (int i = 0; i < 4; i++) {
        uint32_t bo = (uint32_t)(rbase + 32 * i) * 128 + c * 16;
        swo[i] = bo ^ ((bo >> 3) & 0x70);
    }

    auto koffA = [](int ck) -> size_t {
        int sec = ck / SECLEN;
        int kk  = ck - sec * SECLEN;
        int map = (AMAP >> sec) & 1;
        return ((size_t)map * KLOG + (size_t)kk * 64) * 2;
    };
    auto koffB = [](int ck) -> size_t {
        int sec = ck / SECLEN;
        int kk  = ck - sec * SECLEN;
        int map = (BMAP >> sec) & 1;
        return ((size_t)map * KLOG + (size_t)kk * 64) * 2;
    };

#define LOADCHUNK(STG, CK) do {                                            \
        size_t oa_ = koffA(CK), ob_ = koffB(CK);                           \
        uint32_t ab_ = (STG), bb_ = (STG) + 16384;                         \
        cp16(ab_ + swo[0], aRow + oa_);                                    \
        cp16(ab_ + swo[1], aRow + oa_ + rsA);                              \
        cp16(ab_ + swo[2], aRow + oa_ + 2 * rsA);                          \
        cp16(ab_ + swo[3], aRow + oa_ + 3 * rsA);                          \
        cp16(bb_ + swo[0], bRow + ob_);                                    \
        cp16(bb_ + swo[1], bRow + ob_ + rsB);                              \
        cp16(bb_ + swo[2], bRow + ob_ + 2 * rsB);                          \
        cp16(bb_ + swo[3], bRow + ob_ + 3 * rsB);                          \
        asm volatile("cp.async.commit_group;" ::: "memory");               \
    } while (0)

    // ---- ldmatrix per-lane swizzled offsets ----
    uint32_t aoff[2], boff[4];
    {
        int l = lane;
        #pragma unroll
        for (int mt = 0; mt < 2; mt++) {
            int row = warpM + mt * 16 + (l & 15);
            uint32_t cb = (uint32_t)((l >> 4) << 4);
            aoff[mt] = (uint32_t)row * 128 + (cb ^ (((uint32_t)row & 7) << 4));
        }
        #pragma unroll
        for (int ng = 0; ng < 4; ng++) {
            int row = warpN + ng * 16 + (l & 7) + ((l >> 4) << 3);
            uint32_t cb = (uint32_t)(((l >> 3) & 1) << 4);
            boff[ng] = (uint32_t)row * 128 + (cb ^ (((uint32_t)row & 7) << 4));
        }
    }

    float d[2][8][4];
    #pragma unroll
    for (int mt = 0; mt < 2; mt++)
        #pragma unroll
        for (int nt = 0; nt < 8; nt++)
            #pragma unroll
            for (int q = 0; q < 4; q++) d[mt][nt][q] = 0.f;

    LOADCHUNK(st0, 0);
    LOADCHUNK(st1, 1);

    uint32_t stage[3] = { st0, st1, st2 };
    int cur = 0, nxt = 2;

    for (int ck = 0; ck < NUMK; ck++) {
        if (ck < NUMK - 1) asm volatile("cp.async.wait_group 1;" ::: "memory");
        else               asm volatile("cp.async.wait_group 0;" ::: "memory");
        __syncthreads();

        if (ck + 2 < NUMK) {
            LOADCHUNK(stage[nxt], ck + 2);
            nxt = (nxt == 2) ? 0 : nxt + 1;
        }

        uint32_t ab = stage[cur], bb = stage[cur] + 16384;
        cur = (cur == 2) ? 0 : cur + 1;
        #pragma unroll
        for (int ks = 0; ks < 4; ks++) {
            uint32_t kx = (uint32_t)ks << 5;
            uint32_t a[2][4];
            ldsm4(a[0], ab + (aoff[0] ^ kx));
            ldsm4(a[1], ab + (aoff[1] ^ kx));
            #pragma unroll
            for (int ng = 0; ng < 4; ng++) {
                uint32_t bq[4];
                ldsm4(bq, bb + (boff[ng] ^ kx));
                #pragma unroll
                for (int mt = 0; mt < 2; mt++) {
                    mma16816<HALF>(d[mt][2 * ng],     a[mt], bq[0], bq[1]);
                    mma16816<HALF>(d[mt][2 * ng + 1], a[mt], bq[2], bq[3]);
                }
            }
        }
    }
#undef LOADCHUNK

    // ---- epilogue ----
    int trow = lane >> 2, tcol = (lane & 3) * 2;
    #pragma unroll
    for (int mt = 0; mt < 2; mt++) {
        #pragma unroll
        for (int rr = 0; rr < 2; rr++) {
            size_t grow = (size_t)(m0 + warpM + mt * 16 + trow + rr * 8);
            #pragma unroll
            for (int nt = 0; nt < 8; nt++) {
                int gcol = n0 + warpN + nt * 8 + tcol;
                float v0 = d[mt][nt][rr * 2 + 0];
                float v1 = d[mt][nt][rr * 2 + 1];
                if (EPI == 1 || EPI == 3) {
                    float2 bq = *(const float2*)(bias + gcol);
                    float2 aq = *(const float2*)(addend + ((size_t)z * sC + grow * N) + gcol);
                    v0 = (v0 + bq.x + aq.x) * scale;
                    v1 = (v1 + bq.y + aq.y) * scale;
                } else {
                    v0 *= scale; v1 *= scale;
                }
                if (EPI <= 1) {
                    float* cp = Cf + (size_t)z * sC + grow * N + gcol;
                    *(float2*)cp = make_float2(v0, v1);
                } else if (EPI == 3) {
                    __nv_bfloat16* o = (__nv_bfloat16*)Cs +
                        (size_t)z * sC + grow * (size_t)(2 * N) + gcol;
                    uint32_t hi = f2bf2(v0, v1);
                    uint32_t lo = f2bf2(v0 - bfround(v0), v1 - bfround(v1));
                    *(uint32_t*)(o)     = hi;
                    *(uint32_t*)(o + N) = lo;
                } else {   // EPI == 4 : fp16 single
                    __half* o = (__half*)Cs + (size_t)z * sC + grow * (size_t)N + gcol;
                    *(uint32_t*)o = f2h2(v0, v1);
                }
            }
        }
    }
}

// ===========================================================================
// softmax over S=1024: writes f32 in place + single-fp16 copy for K4
// ===========================================================================
__global__ void softmax_f16_kernel(float* __restrict__ attn,
                                   __half* __restrict__ asp)
{
    size_t row = blockIdx.x;
    float* p = attn + row * 1024;
    int tid = threadIdx.x;

    float4 v = *(const float4*)&p[tid * 4];
    __shared__ float sm[8];

    float m = fmaxf(fmaxf(v.x, v.y), fmaxf(v.z, v.w));
    #pragma unroll
    for (int o = 16; o > 0; o >>= 1) m = fmaxf(m, __shfl_xor_sync(0xffffffffu, m, o));
    if ((tid & 31) == 0) sm[tid >> 5] = m;
    __syncthreads();
    float rmax = sm[0];
    #pragma unroll
    for (int w = 1; w < 8; w++) rmax = fmaxf(rmax, sm[w]);

    float e0 = expf(v.x - rmax), e1 = expf(v.y - rmax);
    float e2 = expf(v.z - rmax), e3 = expf(v.w - rmax);

    float s = (e0 + e1) + (e2 + e3);
    #pragma unroll
    for (int o = 16; o > 0; o >>= 1) s += __shfl_xor_sync(0xffffffffu, s, o);
    __syncthreads();
    if ((tid & 31) == 0) sm[tid >> 5] = s;
    __syncthreads();
    float rsum = 0.f;
    #pragma unroll
    for (int w = 0; w < 8; w++) rsum += sm[w];
    float inv = 1.f / rsum;

    float o0 = e0 * inv, o1 = e1 * inv, o2 = e2 * inv, o3 = e3 * inv;
    *(float4*)&p[tid * 4] = make_float4(o0, o1, o2, o3);

    uint32_t h01 = f2h2(o0, o1);
    uint32_t h23 = f2h2(o2, o3);
    *(uint2*)(asp + row * 1024 + tid * 4) = make_uint2(h01, h23);
}

// ===========================================================================
extern "C" void kernel_launch(void* const* d_in, const int* in_sizes, int n_in,
                              void* d_out, int out_size)
{
    const float* x     = (const float*)d_in[0];
    const float* te    = (const float*)d_in[1];
    const float* enc0  = (const float*)d_in[2];
    const float* enc1  = (const float*)d_in[3];
    const float* enc2  = (const float*)d_in[4];
    const float* in_v  = (const float*)d_in[5];
    const float* in_g  = (const float*)d_in[6];
    const float* in_b  = (const float*)d_in[7];
    const float* out_v = (const float*)d_in[8];
    const float* out_g = (const float*)d_in[9];
    const float* out_b = (const float*)d_in[10];

    float* out  = (float*)d_out;
    float* attn = out + (size_t)64 * 1024 * 512;

    __nv_bfloat16 *xsp, *hsp, *esumT, *winsp;
    __half *ctxh, *attnh, *enc2T, *wouth;
    cudaGetSymbolAddress((void**)&xsp,   g_xsplit);
    cudaGetSymbolAddress((void**)&hsp,   g_hsplit);
    cudaGetSymbolAddress((void**)&ctxh,  g_ctx_f16);
    cudaGetSymbolAddress((void**)&attnh, g_attn_f16);
    cudaGetSymbolAddress((void**)&esumT, g_esumT);
    cudaGetSymbolAddress((void**)&enc2T, g_enc2T);
    cudaGetSymbolAddress((void**)&winsp, g_winsplit);
    cudaGetSymbolAddress((void**)&wouth, g_woutsplit);

    // instantiations
    auto K1 = mma_gemm<3, 512, 3, 2, 4, 1024, 1024, false>;
    auto K2 = mma_gemm<0, 512, 3, 2, 4, 1024, 1024, false>;
    auto K4 = mma_gemm<4, 1024, 2, 0, 2, 1024, 2048, true>;
    auto K5 = mma_gemm<1, 512, 2, 0, 2, 512, 1024, true>;
    cudaFuncSetAttribute(K1, cudaFuncAttributeMaxDynamicSharedMemorySize, SMEM_BYTES);
    cudaFuncSetAttribute(K2, cudaFuncAttributeMaxDynamicSharedMemorySize, SMEM_BYTES);
    cudaFuncSetAttribute(K4, cudaFuncAttributeMaxDynamicSharedMemorySize, SMEM_BYTES);
    cudaFuncSetAttribute(K5, cudaFuncAttributeMaxDynamicSharedMemorySize, SMEM_BYTES);

    // side stream + events for fork/join inside graph capture
    cudaStream_t s1;
    cudaStreamCreateWithFlags(&s1, cudaStreamNonBlocking);
    cudaEvent_t eFork, ePrep, eK1, eHalfB;
    cudaEventCreateWithFlags(&eFork,  cudaEventDisableTiming);
    cudaEventCreateWithFlags(&ePrep,  cudaEventDisableTiming);
    cudaEventCreateWithFlags(&eK1,    cudaEventDisableTiming);
    cudaEventCreateWithFlags(&eHalfB, cudaEventDisableTiming);

    // ---- fork ----
    cudaEventRecord(eFork, 0);
    cudaStreamWaitEvent(s1, eFork, 0);

    // side stream: operand prep for K2/K4/K5
    wn_split_f16_kernel<<<512, 256, 0, s1>>>(out_v, out_g, wouth, 512);
    transpose_split_kernel<<<dim3(8, 32, 64), 256, 0, s1>>>(
        enc0, enc1, esumT, 512, 1024, (long long)512 * 1024, (long long)1024 * 1024);
    transpose_split_f16_kernel<<<dim3(16, 16, 64), 256, 0, s1>>>(
        enc2, enc2T, 1024, 512, (long long)1024 * 512, (long long)512 * 2048);
    cudaEventRecord(ePrep, s1);

    // main stream: K1 chain
    wn_split_kernel<<<512, 256>>>(in_v, in_g, winsp, 512);
    asplit_kernel<<<16384, 256>>>(x, xsp);
    K1<<<dim3(4, 512, 1), 256, SMEM_BYTES>>>(
        (const uint16_t*)xsp, (const uint16_t*)winsp, nullptr, hsp,
        512, 0LL, 0LL, 0LL, in_b, te, SQRT_HALF_F);

    // join: main needs esumT before K2
    cudaStreamWaitEvent(0, ePrep, 0);
    cudaEventRecord(eK1, 0);
    cudaStreamWaitEvent(s1, eK1, 0);

    // ---- half-pipelined K2 -> softmax -> K4 (batches 0-31 / 32-63) ----
    const long long sA2 = (long long)1024 * 1024;   // hsp per-batch (elems)
    const long long sB2 = (long long)1024 * 1024;   // esumT per-batch
    const long long sC2 = (long long)1024 * 1024;   // attn per-batch
    const long long sA4 = (long long)1024 * 1024;   // attn_f16 per-batch
    const long long sB4 = (long long)512 * 2048;    // enc2T f16 per-batch
    const long long sC4 = (long long)1024 * 512;    // ctx_f16 per-batch

    // main: half A
    K2<<<dim3(8, 8, 32), 256, SMEM_BYTES>>>(
        (const uint16_t*)hsp, (const uint16_t*)esumT, attn, nullptr,
        1024, sA2, sB2, sC2, nullptr, nullptr, 1.0f);
    softmax_f16_kernel<<<32768, 256>>>(attn, attnh);
    K4<<<dim3(4, 8, 32), 256, SMEM_BYTES>>>(
        (const uint16_t*)attnh, (const uint16_t*)enc2T, nullptr, ctxh,
        512, sA4, sB4, sC4, nullptr, nullptr, 32.0f);

    // side: half B
    K2<<<dim3(8, 8, 32), 256, SMEM_BYTES, s1>>>(
        (const uint16_t*)(hsp + 32 * sA2), (const uint16_t*)(esumT + 32 * sB2),
        attn + 32 * sC2, nullptr, 1024, sA2, sB2, sC2, nullptr, nullptr, 1.0f);
    softmax_f16_kernel<<<32768, 256, 0, s1>>>(attn + 32 * sC2, attnh + 32 * sA4);
    K4<<<dim3(4, 8, 32), 256, SMEM_BYTES, s1>>>(
        (const uint16_t*)(attnh + 32 * sA4), (const uint16_t*)(enc2T + 32 * sB4),
        nullptr, ctxh + 32 * sC4, 512, sA4, sB4, sC4, nullptr, nullptr, 32.0f);
    cudaEventRecord(eHalfB, s1);

    // join before K5
    cudaStreamWaitEvent(0, eHalfB, 0);

    // K5: out = (ctx@Wout^T + b + x)*sqrt(.5)  f32, addend = x
    K5<<<dim3(4, 512, 1), 256, SMEM_BYTES>>>(
        (const uint16_t*)ctxh, (const uint16_t*)wouth, out, nullptr,
        512, 0LL, 0LL, 0LL, out_b, x, SQRT_HALF_F);
}

// round 10
// speedup vs baseline: 1.5230x; 1.1898x over previous
#include <cuda_runtime.h>
#include <cuda_bf16.h>
#include <cuda_fp16.h>
#include <math.h>
#include <stdint.h>

// ===========================================================================
// AttentionLayer via mma.sync split GEMMs (fp32 accumulate in registers)
// B=64, T=1024, S=1024, C=E=512. Output = concat(out [B,T,C], attn [B,T,S])
//
// K1 (h = x@Win^T+b+te)  : 3-term bf16 split (scores amplify h errors)
// K2 (scores = h@esum)   : 3-term bf16 split
// K4 (ctx = attn@enc2)   : 1-pass fp16 (attn_f16 · enc2_f16)
// K5 (out = ctx@Wout^T+.): 1-pass fp16 (ctx_f16 · W_f16)
// ===========================================================================

static const float SQRT_HALF_F = 0.70710678118654752440f;

// ------------------------------ scratch ------------------------------------
__device__ __nv_bfloat16 g_xsplit  [(size_t)65536 * 1024];
__device__ __nv_bfloat16 g_hsplit  [(size_t)65536 * 1024];
__device__ __half        g_ctx_f16 [(size_t)65536 * 512];
__device__ __half        g_attn_f16[(size_t)65536 * 1024];
__device__ __nv_bfloat16 g_esumT   [(size_t)64 * 1024 * 1024];
__device__ __half        g_enc2T   [(size_t)64 * 512 * 1024];
__device__ __nv_bfloat16 g_winsplit [512 * 1024];
__device__ __half        g_wout_f16 [512 * 512];

// ------------------------------ helpers ------------------------------------
__device__ __forceinline__ uint32_t smem_u32(const void* p) {
    uint32_t a;
    asm("{ .reg .u64 t; cvta.to.shared.u64 t, %1; cvt.u32.u64 %0, t; }"
        : "=r"(a) : "l"(p));
    return a;
}

// pack two floats -> bf16x2 / f16x2 (first arg at lower address)
__device__ __forceinline__ uint32_t f2bf2(float lo, float hi) {
    uint32_t r;
    asm("cvt.rn.bf16x2.f32 %0, %1, %2;" : "=r"(r) : "f"(hi), "f"(lo));
    return r;
}
__device__ __forceinline__ uint32_t f2h2(float lo, float hi) {
    uint32_t r;
    asm("cvt.rn.f16x2.f32 %0, %1, %2;" : "=r"(r) : "f"(hi), "f"(lo));
    return r;
}
__device__ __forceinline__ float bfround(float v) {
    return __bfloat162float(__float2bfloat16(v));
}

__device__ __forceinline__ void cp16(uint32_t s, const void* g) {
    asm volatile("cp.async.cg.shared.global [%0], [%1], 16;" :: "r"(s), "l"(g));
}

__device__ __forceinline__ void ldsm4(uint32_t* r, uint32_t addr) {
    asm volatile("ldmatrix.sync.aligned.m8n8.x4.shared.b16 {%0,%1,%2,%3}, [%4];"
                 : "=r"(r[0]), "=r"(r[1]), "=r"(r[2]), "=r"(r[3]) : "r"(addr));
}

template <bool HALF>
__device__ __forceinline__ void mma16816(float* d, const uint32_t* a,
                                         uint32_t b0, uint32_t b1) {
    if (HALF)
        asm volatile(
            "mma.sync.aligned.m16n8k16.row.col.f32.f16.f16.f32 "
            "{%0,%1,%2,%3}, {%4,%5,%6,%7}, {%8,%9}, {%0,%1,%2,%3};"
            : "+f"(d[0]), "+f"(d[1]), "+f"(d[2]), "+f"(d[3])
            : "r"(a[0]), "r"(a[1]), "r"(a[2]), "r"(a[3]), "r"(b0), "r"(b1));
    else
        asm volatile(
            "mma.sync.aligned.m16n8k16.row.col.f32.bf16.bf16.f32 "
            "{%0,%1,%2,%3}, {%4,%5,%6,%7}, {%8,%9}, {%0,%1,%2,%3};"
            : "+f"(d[0]), "+f"(d[1]), "+f"(d[2]), "+f"(d[3])
            : "r"(a[0]), "r"(a[1]), "r"(a[2]), "r"(a[3]), "r"(b0), "r"(b1));
}

// ===========================================================================
// weight-norm + split [hi|lo] bf16: one block per row, cols=512
// ===========================================================================
__global__ void wn_split_kernel(const float* __restrict__ v, const float* __restrict__ g,
                                __nv_bfloat16* __restrict__ w, int cols)
{
    int r = blockIdx.x;
    int tid = threadIdx.x;
    const float* vr = v + (size_t)r * cols;

    float ss = 0.f;
    for (int c = tid; c < cols; c += blockDim.x) { float t = vr[c]; ss += t * t; }
    __shared__ float sm[32];
    #pragma unroll
    for (int o = 16; o > 0; o >>= 1) ss += __shfl_down_sync(0xffffffffu, ss, o);
    int warp = tid >> 5, lane = tid & 31;
    if (lane == 0) sm[warp] = ss;
    __syncthreads();
    int nw = blockDim.x >> 5;
    if (warp == 0) {
        float s2 = (lane < nw) ? sm[lane] : 0.f;
        #pragma unroll
        for (int o = 16; o > 0; o >>= 1) s2 += __shfl_down_sync(0xffffffffu, s2, o);
        if (lane == 0) sm[0] = s2;
    }
    __syncthreads();
    float scale = g[r] / sqrtf(sm[0]);
    __nv_bfloat16* wr = w + (size_t)r * (2 * cols);
    for (int c = tid; c < cols; c += blockDim.x) {
        float wv = vr[c] * scale;
        __nv_bfloat16 h = __float2bfloat16(wv);
        __nv_bfloat16 l = __float2bfloat16(wv - __bfloat162float(h));
        wr[c] = h;
        wr[cols + c] = l;
    }
}

// ===========================================================================
// weight-norm, single fp16 (for W_out): one block per row
// ===========================================================================
__global__ void wn_f16_kernel(const float* __restrict__ v, const float* __restrict__ g,
                              __half* __restrict__ w, int cols)
{
    int r = blockIdx.x;
    int tid = threadIdx.x;
    const float* vr = v + (size_t)r * cols;

    float ss = 0.f;
    for (int c = tid; c < cols; c += blockDim.x) { float t = vr[c]; ss += t * t; }
    __shared__ float sm[32];
    #pragma unroll
    for (int o = 16; o > 0; o >>= 1) ss += __shfl_down_sync(0xffffffffu, ss, o);
    int warp = tid >> 5, lane = tid & 31;
    if (lane == 0) sm[warp] = ss;
    __syncthreads();
    int nw = blockDim.x >> 5;
    if (warp == 0) {
        float s2 = (lane < nw) ? sm[lane] : 0.f;
        #pragma unroll
        for (int o = 16; o > 0; o >>= 1) s2 += __shfl_down_sync(0xffffffffu, s2, o);
        if (lane == 0) sm[0] = s2;
    }
    __syncthreads();
    float scale = g[r] / sqrtf(sm[0]);
    __half* wr = w + (size_t)r * cols;
    for (int c = tid; c < cols; c += blockDim.x)
        wr[c] = __float2half_rn(vr[c] * scale);
}

// ===========================================================================
// A-split [hi|lo] bf16:  x [65536,512] -> [65536,1024]
// ===========================================================================
__global__ void asplit_kernel(const float* __restrict__ in, __nv_bfloat16* __restrict__ out)
{
    size_t idx = (size_t)blockIdx.x * 256 + threadIdx.x;
    size_t row = idx >> 6;
    int g = (int)(idx & 63);
    const float* p = in + row * 512 + g * 8;
    float4 f0 = *(const float4*)p;
    float4 f1 = *(const float4*)(p + 4);
    float v[8] = {f0.x, f0.y, f0.z, f0.w, f1.x, f1.y, f1.z, f1.w};
    uint32_t hi[4], lo[4];
    #pragma unroll
    for (int q = 0; q < 4; q++) {
        hi[q] = f2bf2(v[2*q], v[2*q+1]);
        lo[q] = f2bf2(v[2*q] - bfround(v[2*q]), v[2*q+1] - bfround(v[2*q+1]));
    }
    __nv_bfloat16* o = out + row * 1024 + g * 8;
    *(uint4*)(o)       = *(uint4*)hi;
    *(uint4*)(o + 512) = *(uint4*)lo;
}

// ===========================================================================
// transpose + split [hi|lo] bf16: in0(+in1) [R, Cc] per batch -> out [Cc, 2R]
// ===========================================================================
__global__ void transpose_split_kernel(const float* __restrict__ in0,
                                       const float* __restrict__ in1,
                                       __nv_bfloat16* __restrict__ out,
                                       int R, int Cc, long long sIn, long long sOut)
{
    __shared__ float tile[64][33];
    int b = blockIdx.z;
    const float* A0 = in0 + (size_t)b * sIn;
    const float* A1 = in1 ? in1 + (size_t)b * sIn : nullptr;
    __nv_bfloat16* O = out + (size_t)b * sOut;
    int r0 = blockIdx.x * 64;
    int c0 = blockIdx.y * 32;
    int tid = threadIdx.x;

    #pragma unroll
    for (int i = 0; i < 8; i++) {
        int idx = i * 256 + tid;
        int rr = idx >> 5, cc = idx & 31;
        size_t off = (size_t)(r0 + rr) * Cc + c0 + cc;
        float vv = A0[off];
        if (A1) vv += A1[off];
        tile[rr][cc] = vv;
    }
    __syncthreads();

    int j = tid >> 3;
    int g = tid & 7;
    float v[8];
    #pragma unroll
    for (int u = 0; u < 8; u++) v[u] = tile[g * 8 + u][j];
    uint32_t hi[4], lo[4];
    #pragma unroll
    for (int p = 0; p < 4; p++) {
        hi[p] = f2bf2(v[2*p], v[2*p+1]);
        lo[p] = f2bf2(v[2*p] - bfround(v[2*p]), v[2*p+1] - bfround(v[2*p+1]));
    }
    __nv_bfloat16* ob = O + (size_t)(c0 + j) * (2 * R) + r0 + g * 8;
    *(uint4*)(ob)     = *(uint4*)hi;
    *(uint4*)(ob + R) = *(uint4*)lo;
}

// ===========================================================================
// transpose, single fp16: enc2 [R, Cc] per batch -> out [Cc, R]
// ===========================================================================
__global__ void transpose_f16_kernel(const float* __restrict__ in0,
                                     __half* __restrict__ out,
                                     int R, int Cc, long long sIn, long long sOut)
{
    __shared__ float tile[64][33];
    int b = blockIdx.z;
    const float* A0 = in0 + (size_t)b * sIn;
    __half* O = out + (size_t)b * sOut;
    int r0 = blockIdx.x * 64;
    int c0 = blockIdx.y * 32;
    int tid = threadIdx.x;

    #pragma unroll
    for (int i = 0; i < 8; i++) {
        int idx = i * 256 + tid;
        int rr = idx >> 5, cc = idx & 31;
        tile[rr][cc] = A0[(size_t)(r0 + rr) * Cc + c0 + cc];
    }
    __syncthreads();

    int j = tid >> 3;
    int g = tid & 7;
    float v[8];
    #pragma unroll
    for (int u = 0; u < 8; u++) v[u] = tile[g * 8 + u][j];
    uint32_t hv[4];
    #pragma unroll
    for (int p = 0; p < 4; p++) hv[p] = f2h2(v[2*p], v[2*p+1]);
    __half* ob = O + (size_t)(c0 + j) * R + r0 + g * 8;
    *(uint4*)(ob) = *(uint4*)hv;
}

// ===========================================================================
// mma.sync GEMM: C[128x128] = A x B^T over NSEC remapped K-sections.
// A row length AROW elems; B row length BROW. Section s uses +KLOG offset
// iff (AMAP>>s)&1 (resp BMAP). bf16 or fp16 operands per HALF.
// EPI: 0 = f32 C=acc*scale ; 1 = f32 C=(acc+bias+addend)*scale
//      3 = bf16 split [hi|lo] (acc+bias+addend)*scale ; 4 = fp16 single, *scale
// ===========================================================================
#define SMEM_BYTES 98304

template <int EPI, int KLOG, int NSEC, int AMAP, int BMAP, int AROW, int BROW, bool HALF>
__global__ __launch_bounds__(256, 2)
void mma_gemm(const uint16_t* __restrict__ A,
              const uint16_t* __restrict__ B,
              float* __restrict__ Cf, void* __restrict__ Cs,
              int N,
              long long sA, long long sB, long long sC,
              const float* __restrict__ bias,
              const float* __restrict__ addend,
              float scale)
{
    constexpr int SECLEN = KLOG / 64;      // chunks per section
    constexpr int NUMK   = NSEC * SECLEN;

    extern __shared__ __align__(1024) char smem[];
    uint32_t sbase = smem_u32(smem);
    const uint32_t st0 = sbase, st1 = sbase + 32768, st2 = sbase + 65536;

    int tid = threadIdx.x, wid = tid >> 5, lane = tid & 31;
    int z = blockIdx.z;
    A += (size_t)z * sA;
    B += (size_t)z * sB;
    int m0 = blockIdx.y * 128, n0 = blockIdx.x * 128;
    int warpM = (wid >> 1) * 32, warpN = (wid & 1) * 64;

    // ---- loader mapping: 4x16B cp.async per operand per chunk ----
    int c = tid & 7, rbase = tid >> 3;
    const size_t rsA = (size_t)32 * AROW * 2;   // 32 rows in bytes
    const size_t rsB = (size_t)32 * BROW * 2;
    const char* aRow = (const char*)(A + (size_t)(m0 + rbase) * AROW + c * 8);
    const char* bRow = (const char*)(B + (size_t)(n0 + rbase) * BROW + c * 8);
    uint32_t swo[4];
    #pragma unroll
    for (int i = 0; i < 4; i++) {
        uint32_t bo = (uint32_t)(rbase + 32 * i) * 128 + c * 16;
        swo[i] = bo ^ ((bo >> 3) & 0x70);
    }

    auto koffA = [](int ck) -> size_t {
        int sec = ck / SECLEN;
        int kk  = ck - sec * SECLEN;
        int map = (AMAP >> sec) & 1;
        return ((size_t)map * KLOG + (size_t)kk * 64) * 2;
    };
    auto koffB = [](int ck) -> size_t {
        int sec = ck / SECLEN;
        int kk  = ck - sec * SECLEN;
        int map = (BMAP >> sec) & 1;
        return ((size_t)map * KLOG + (size_t)kk * 64) * 2;
    };

#define LOADCHUNK(STG, CK) do {                                            \
        size_t oa_ = koffA(CK), ob_ = koffB(CK);                           \
        uint32_t ab_ = (STG), bb_ = (STG) + 16384;                         \
        cp16(ab_ + swo[0], aRow + oa_);                                    \
        cp16(ab_ + swo[1], aRow + oa_ + rsA);                              \
        cp16(ab_ + swo[2], aRow + oa_ + 2 * rsA);                          \
        cp16(ab_ + swo[3], aRow + oa_ + 3 * rsA);                          \
        cp16(bb_ + swo[0], bRow + ob_);                                    \
        cp16(bb_ + swo[1], bRow + ob_ + rsB);                              \
        cp16(bb_ + swo[2], bRow + ob_ + 2 * rsB);                          \
        cp16(bb_ + swo[3], bRow + ob_ + 3 * rsB);                          \
        asm volatile("cp.async.commit_group;" ::: "memory");               \
    } while (0)

    // ---- ldmatrix per-lane swizzled offsets ----
    uint32_t aoff[2], boff[4];
    {
        int l = lane;
        #pragma unroll
        for (int mt = 0; mt < 2; mt++) {
            int row = warpM + mt * 16 + (l & 15);
            uint32_t cb = (uint32_t)((l >> 4) << 4);
            aoff[mt] = (uint32_t)row * 128 + (cb ^ (((uint32_t)row & 7) << 4));
        }
        #pragma unroll
        for (int ng = 0; ng < 4; ng++) {
            int row = warpN + ng * 16 + (l & 7) + ((l >> 4) << 3);
            uint32_t cb = (uint32_t)(((l >> 3) & 1) << 4);
            boff[ng] = (uint32_t)row * 128 + (cb ^ (((uint32_t)row & 7) << 4));
        }
    }

    float d[2][8][4];
    #pragma unroll
    for (int mt = 0; mt < 2; mt++)
        #pragma unroll
        for (int nt = 0; nt < 8; nt++)
            #pragma unroll
            for (int q = 0; q < 4; q++) d[mt][nt][q] = 0.f;

    LOADCHUNK(st0, 0);
    LOADCHUNK(st1, 1);

    uint32_t stage[3] = { st0, st1, st2 };
    int cur = 0, nxt = 2;

    for (int ck = 0; ck < NUMK; ck++) {
        if (ck < NUMK - 1) asm volatile("cp.async.wait_group 1;" ::: "memory");
        else               asm volatile("cp.async.wait_group 0;" ::: "memory");
        __syncthreads();

        if (ck + 2 < NUMK) {
            LOADCHUNK(stage[nxt], ck + 2);
            nxt = (nxt == 2) ? 0 : nxt + 1;
        }

        uint32_t ab = stage[cur], bb = stage[cur] + 16384;
        cur = (cur == 2) ? 0 : cur + 1;
        #pragma unroll
        for (int ks = 0; ks < 4; ks++) {
            uint32_t kx = (uint32_t)ks << 5;
            uint32_t a[2][4];
            ldsm4(a[0], ab + (aoff[0] ^ kx));
            ldsm4(a[1], ab + (aoff[1] ^ kx));
            #pragma unroll
            for (int ng = 0; ng < 4; ng++) {
                uint32_t bq[4];
                ldsm4(bq, bb + (boff[ng] ^ kx));
                #pragma unroll
                for (int mt = 0; mt < 2; mt++) {
                    mma16816<HALF>(d[mt][2 * ng],     a[mt], bq[0], bq[1]);
                    mma16816<HALF>(d[mt][2 * ng + 1], a[mt], bq[2], bq[3]);
                }
            }
        }
    }
#undef LOADCHUNK

    // ---- epilogue ----
    int trow = lane >> 2, tcol = (lane & 3) * 2;
    #pragma unroll
    for (int mt = 0; mt < 2; mt++) {
        #pragma unroll
        for (int rr = 0; rr < 2; rr++) {
            size_t grow = (size_t)(m0 + warpM + mt * 16 + trow + rr * 8);
            #pragma unroll
            for (int nt = 0; nt < 8; nt++) {
                int gcol = n0 + warpN + nt * 8 + tcol;
                float v0 = d[mt][nt][rr * 2 + 0];
                float v1 = d[mt][nt][rr * 2 + 1];
                if (EPI == 1 || EPI == 3) {
                    float2 bq = *(const float2*)(bias + gcol);
                    float2 aq = *(const float2*)(addend + ((size_t)z * sC + grow * N) + gcol);
                    v0 = (v0 + bq.x + aq.x) * scale;
                    v1 = (v1 + bq.y + aq.y) * scale;
                } else {
                    v0 *= scale; v1 *= scale;
                }
                if (EPI <= 1) {
                    float* cp = Cf + (size_t)z * sC + grow * N + gcol;
                    *(float2*)cp = make_float2(v0, v1);
                } else if (EPI == 3) {
                    __nv_bfloat16* o = (__nv_bfloat16*)Cs +
                        (size_t)z * sC + grow * (size_t)(2 * N) + gcol;
                    uint32_t hi = f2bf2(v0, v1);
                    uint32_t lo = f2bf2(v0 - bfround(v0), v1 - bfround(v1));
                    *(uint32_t*)(o)     = hi;
                    *(uint32_t*)(o + N) = lo;
                } else {   // EPI == 4 : fp16 single
                    __half* o = (__half*)Cs + (size_t)z * sC + grow * (size_t)N + gcol;
                    *(uint32_t*)o = f2h2(v0, v1);
                }
            }
        }
    }
}

// ===========================================================================
// softmax over S=1024: writes f32 in place + single-fp16 copy for K4
// ===========================================================================
__global__ void softmax_f16_kernel(float* __restrict__ attn,
                                   __half* __restrict__ asp)
{
    size_t row = blockIdx.x;
    float* p = attn + row * 1024;
    int tid = threadIdx.x;

    float4 v = *(const float4*)&p[tid * 4];
    __shared__ float sm[8];

    float m = fmaxf(fmaxf(v.x, v.y), fmaxf(v.z, v.w));
    #pragma unroll
    for (int o = 16; o > 0; o >>= 1) m = fmaxf(m, __shfl_xor_sync(0xffffffffu, m, o));
    if ((tid & 31) == 0) sm[tid >> 5] = m;
    __syncthreads();
    float rmax = sm[0];
    #pragma unroll
    for (int w = 1; w < 8; w++) rmax = fmaxf(rmax, sm[w]);

    float e0 = expf(v.x - rmax), e1 = expf(v.y - rmax);
    float e2 = expf(v.z - rmax), e3 = expf(v.w - rmax);

    float s = (e0 + e1) + (e2 + e3);
    #pragma unroll
    for (int o = 16; o > 0; o >>= 1) s += __shfl_xor_sync(0xffffffffu, s, o);
    __syncthreads();
    if ((tid & 31) == 0) sm[tid >> 5] = s;
    __syncthreads();
    float rsum = 0.f;
    #pragma unroll
    for (int w = 0; w < 8; w++) rsum += sm[w];
    float inv = 1.f / rsum;

    float o0 = e0 * inv, o1 = e1 * inv, o2 = e2 * inv, o3 = e3 * inv;
    *(float4*)&p[tid * 4] = make_float4(o0, o1, o2, o3);

    uint32_t h01 = f2h2(o0, o1);
    uint32_t h23 = f2h2(o2, o3);
    *(uint2*)(asp + row * 1024 + tid * 4) = make_uint2(h01, h23);
}

// ===========================================================================
extern "C" void kernel_launch(void* const* d_in, const int* in_sizes, int n_in,
                              void* d_out, int out_size)
{
    const float* x     = (const float*)d_in[0];
    const float* te    = (const float*)d_in[1];
    const float* enc0  = (const float*)d_in[2];
    const float* enc1  = (const float*)d_in[3];
    const float* enc2  = (const float*)d_in[4];
    const float* in_v  = (const float*)d_in[5];
    const float* in_g  = (const float*)d_in[6];
    const float* in_b  = (const float*)d_in[7];
    const float* out_v = (const float*)d_in[8];
    const float* out_g = (const float*)d_in[9];
    const float* out_b = (const float*)d_in[10];

    float* out  = (float*)d_out;
    float* attn = out + (size_t)64 * 1024 * 512;

    __nv_bfloat16 *xsp, *hsp, *esumT, *winsp;
    __half *ctxh, *attnh, *enc2T, *wouth;
    cudaGetSymbolAddress((void**)&xsp,   g_xsplit);
    cudaGetSymbolAddress((void**)&hsp,   g_hsplit);
    cudaGetSymbolAddress((void**)&ctxh,  g_ctx_f16);
    cudaGetSymbolAddress((void**)&attnh, g_attn_f16);
    cudaGetSymbolAddress((void**)&esumT, g_esumT);
    cudaGetSymbolAddress((void**)&enc2T, g_enc2T);
    cudaGetSymbolAddress((void**)&winsp, g_winsplit);
    cudaGetSymbolAddress((void**)&wouth, g_wout_f16);

    // instantiations
    auto K1 = mma_gemm<3, 512, 3, 2, 4, 1024, 1024, false>;
    auto K2 = mma_gemm<0, 512, 3, 2, 4, 1024, 1024, false>;
    auto K4 = mma_gemm<4, 1024, 1, 0, 0, 1024, 1024, true>;   // single pass
    auto K5 = mma_gemm<1, 512, 1, 0, 0, 512, 512, true>;      // single pass
    cudaFuncSetAttribute(K1, cudaFuncAttributeMaxDynamicSharedMemorySize, SMEM_BYTES);
    cudaFuncSetAttribute(K2, cudaFuncAttributeMaxDynamicSharedMemorySize, SMEM_BYTES);
    cudaFuncSetAttribute(K4, cudaFuncAttributeMaxDynamicSharedMemorySize, SMEM_BYTES);
    cudaFuncSetAttribute(K5, cudaFuncAttributeMaxDynamicSharedMemorySize, SMEM_BYTES);

    // side stream + events for fork/join inside graph capture
    cudaStream_t s1;
    cudaStreamCreateWithFlags(&s1, cudaStreamNonBlocking);
    cudaEvent_t eFork, ePrep, eK1, eHalfB;
    cudaEventCreateWithFlags(&eFork,  cudaEventDisableTiming);
    cudaEventCreateWithFlags(&ePrep,  cudaEventDisableTiming);
    cudaEventCreateWithFlags(&eK1,    cudaEventDisableTiming);
    cudaEventCreateWithFlags(&eHalfB, cudaEventDisableTiming);

    // ---- fork ----
    cudaEventRecord(eFork, 0);
    cudaStreamWaitEvent(s1, eFork, 0);

    // side stream: operand prep for K2/K4/K5
    wn_f16_kernel<<<512, 256, 0, s1>>>(out_v, out_g, wouth, 512);
    transpose_split_kernel<<<dim3(8, 32, 64), 256, 0, s1>>>(
        enc0, enc1, esumT, 512, 1024, (long long)512 * 1024, (long long)1024 * 1024);
    transpose_f16_kernel<<<dim3(16, 16, 64), 256, 0, s1>>>(
        enc2, enc2T, 1024, 512, (long long)1024 * 512, (long long)512 * 1024);
    cudaEventRecord(ePrep, s1);

    // main stream: K1 chain
    wn_split_kernel<<<512, 256>>>(in_v, in_g, winsp, 512);
    asplit_kernel<<<16384, 256>>>(x, xsp);
    K1<<<dim3(4, 512, 1), 256, SMEM_BYTES>>>(
        (const uint16_t*)xsp, (const uint16_t*)winsp, nullptr, hsp,
        512, 0LL, 0LL, 0LL, in_b, te, SQRT_HALF_F);

    // join: main needs esumT before K2
    cudaStreamWaitEvent(0, ePrep, 0);
    cudaEventRecord(eK1, 0);
    cudaStreamWaitEvent(s1, eK1, 0);

    // ---- half-pipelined K2 -> softmax -> K4 (batches 0-31 / 32-63) ----
    const long long sA2 = (long long)1024 * 1024;   // hsp per-batch (elems)
    const long long sB2 = (long long)1024 * 1024;   // esumT per-batch
    const long long sC2 = (long long)1024 * 1024;   // attn per-batch
    const long long sA4 = (long long)1024 * 1024;   // attn_f16 per-batch
    const long long sB4 = (long long)512 * 1024;    // enc2T f16 per-batch
    const long long sC4 = (long long)1024 * 512;    // ctx_f16 per-batch

    // main: half A
    K2<<<dim3(8, 8, 32), 256, SMEM_BYTES>>>(
        (const uint16_t*)hsp, (const uint16_t*)esumT, attn, nullptr,
        1024, sA2, sB2, sC2, nullptr, nullptr, 1.0f);
    softmax_f16_kernel<<<32768, 256>>>(attn, attnh);
    K4<<<dim3(4, 8, 32), 256, SMEM_BYTES>>>(
        (const uint16_t*)attnh, (const uint16_t*)enc2T, nullptr, ctxh,
        512, sA4, sB4, sC4, nullptr, nullptr, 32.0f);

    // side: half B
    K2<<<dim3(8, 8, 32), 256, SMEM_BYTES, s1>>>(
        (const uint16_t*)(hsp + 32 * sA2), (const uint16_t*)(esumT + 32 * sB2),
        attn + 32 * sC2, nullptr, 1024, sA2, sB2, sC2, nullptr, nullptr, 1.0f);
    softmax_f16_kernel<<<32768, 256, 0, s1>>>(attn + 32 * sC2, attnh + 32 * sA4);
    K4<<<dim3(4, 8, 32), 256, SMEM_BYTES, s1>>>(
        (const uint16_t*)(attnh + 32 * sA4), (const uint16_t*)(enc2T + 32 * sB4),
        nullptr, ctxh + 32 * sC4, 512, sA4, sB4, sC4, nullptr, nullptr, 32.0f);
    cudaEventRecord(eHalfB, s1);

    // join before K5
    cudaStreamWaitEvent(0, eHalfB, 0);

    // K5: out = (ctx@Wout^T + b + x)*sqrt(.5)  f32, addend = x
    K5<<<dim3(4, 512, 1), 256, SMEM_BYTES>>>(
        (const uint16_t*)ctxh, (const uint16_t*)wouth, out, nullptr,
        512, 0LL, 0LL, 0LL, out_b, x, SQRT_HALF_F);
}